// round 10
// baseline (speedup 1.0000x reference)
#include <cuda_runtime.h>
#include <math.h>
#include <stdint.h>

#define BATCH 32
#define LEN   300
#define DM    256
#define DI    512
#define DS    16
#define DR    16
#define NL    4
#define NT    (BATCH * LEN)   // 9600
#define EPSL  1e-5f

// ---------------- scratch ----------------
__device__ float g_x  [NT * DM];
__device__ float g_res[NT * DM];
__device__ float g_h  [NT * DM];
__device__ float g_xz [NT * 2 * DI];
__device__ float g_xc [NT * DI];
__device__ float g_dbl[NT * 48];
__device__ float g_y  [NT * DI];
__device__ float g_o  [NT * DM];

// ---------------- tf32 helpers ----------------
__device__ __forceinline__ float to_tf32(float x) {
    float r;
    asm("cvt.rna.tf32.f32 %0, %1;" : "=f"(r) : "f"(x));
    return r;
}
__device__ __forceinline__ void mma_tf32_16x8x8(
        float& d0, float& d1, float& d2, float& d3,
        uint32_t a0, uint32_t a1, uint32_t a2, uint32_t a3,
        uint32_t b0, uint32_t b1) {
    asm volatile(
        "mma.sync.aligned.m16n8k8.row.col.f32.tf32.tf32.f32 "
        "{%0,%1,%2,%3}, {%4,%5,%6,%7}, {%8,%9}, {%0,%1,%2,%3};"
        : "+f"(d0), "+f"(d1), "+f"(d2), "+f"(d3)
        : "r"(a0), "r"(a1), "r"(a2), "r"(a3), "r"(b0), "r"(b1));
}

// ================ TF32 MMA GEMM: C(MxN) = A(MxK) * B(N,K)^T ================
// BM=128, BN=128, BK=16; 128 threads = 4 warps, warp tile 64x64.
// k interleaved within groups of 8 (slot=(k&3)*2+(k>>2)) so fragment pairs
// (qc, qc+4) are adjacent -> LDS.64, conflict-free with row stride SA=24.
#define SA 24
__global__ __launch_bounds__(128, 2) void mmagemm(
        const float* __restrict__ A, int lda,
        const float* __restrict__ Bw,
        float* __restrict__ C, int N, int K, int ldc) {
    __shared__ float As[2][128 * SA];
    __shared__ float Bs[2][128 * SA];

    const int tid  = threadIdx.x;
    const int lane = tid & 31;
    const int wid  = tid >> 5;          // 0..3
    const int wm   = wid >> 1;          // 0..1
    const int wn   = wid & 1;           // 0..1
    const int bm   = blockIdx.y * 128;
    const int bn   = blockIdx.x * 128;

    const int trow = tid;               // one full 16-float row per thread
    const bool bok = (bn + trow) < N;

    const float* Ag = A + (size_t)(bm + trow) * lda;
    const float* Bg = Bw + (size_t)(bn + trow) * K;

    float acc[4][8][4];
    #pragma unroll
    for (int mt = 0; mt < 4; mt++)
        #pragma unroll
        for (int nt = 0; nt < 8; nt++)
            #pragma unroll
            for (int e = 0; e < 4; e++) acc[mt][nt][e] = 0.f;

    float4 a0, a1, a2, a3, b0v, b1v, b2v, b3v;
    a0 = *(const float4*)(Ag);      a1 = *(const float4*)(Ag + 4);
    a2 = *(const float4*)(Ag + 8);  a3 = *(const float4*)(Ag + 12);
    b0v = b1v = b2v = b3v = make_float4(0.f, 0.f, 0.f, 0.f);
    if (bok) {
        b0v = *(const float4*)(Bg);      b1v = *(const float4*)(Bg + 4);
        b2v = *(const float4*)(Bg + 8);  b3v = *(const float4*)(Bg + 12);
    }

    // interleaved commit: slots[0..3]=(k0,k4,k1,k5), [4..7]=(k2,k6,k3,k7), etc.
    #define COMMIT(stg) do {                                                   \
        float* as = As[stg] + trow * SA;                                       \
        float* bs = Bs[stg] + trow * SA;                                       \
        as[0]=to_tf32(a0.x); as[1]=to_tf32(a1.x); as[2]=to_tf32(a0.y); as[3]=to_tf32(a1.y); \
        as[4]=to_tf32(a0.z); as[5]=to_tf32(a1.z); as[6]=to_tf32(a0.w); as[7]=to_tf32(a1.w); \
        as[8]=to_tf32(a2.x); as[9]=to_tf32(a3.x); as[10]=to_tf32(a2.y); as[11]=to_tf32(a3.y); \
        as[12]=to_tf32(a2.z); as[13]=to_tf32(a3.z); as[14]=to_tf32(a2.w); as[15]=to_tf32(a3.w); \
        bs[0]=to_tf32(b0v.x); bs[1]=to_tf32(b1v.x); bs[2]=to_tf32(b0v.y); bs[3]=to_tf32(b1v.y); \
        bs[4]=to_tf32(b0v.z); bs[5]=to_tf32(b1v.z); bs[6]=to_tf32(b0v.w); bs[7]=to_tf32(b1v.w); \
        bs[8]=to_tf32(b2v.x); bs[9]=to_tf32(b3v.x); bs[10]=to_tf32(b2v.y); bs[11]=to_tf32(b3v.y); \
        bs[12]=to_tf32(b2v.z); bs[13]=to_tf32(b3v.z); bs[14]=to_tf32(b2v.w); bs[15]=to_tf32(b3v.w); \
    } while (0)

    COMMIT(0);
    __syncthreads();

    const int qr = lane >> 2, qc = lane & 3;
    const int KT = K >> 4;
    for (int kt = 0; kt < KT; kt++) {
        const int cur = kt & 1;
        if (kt + 1 < KT) {
            const int off = (kt + 1) * 16;
            a0 = *(const float4*)(Ag + off);      a1 = *(const float4*)(Ag + off + 4);
            a2 = *(const float4*)(Ag + off + 8);  a3 = *(const float4*)(Ag + off + 12);
            if (bok) {
                b0v = *(const float4*)(Bg + off);      b1v = *(const float4*)(Bg + off + 4);
                b2v = *(const float4*)(Bg + off + 8);  b3v = *(const float4*)(Bg + off + 12);
            }
        }
        #pragma unroll
        for (int ks = 0; ks < 2; ks++) {
            const int kc = ks * 8 + 2 * qc;
            uint32_t af[4][4];
            #pragma unroll
            for (int mt = 0; mt < 4; mt++) {
                const int r = wm * 64 + mt * 16 + qr;
                float2 lo = *(const float2*)&As[cur][(r    ) * SA + kc];
                float2 hi = *(const float2*)&As[cur][(r + 8) * SA + kc];
                af[mt][0] = __float_as_uint(lo.x);
                af[mt][1] = __float_as_uint(hi.x);
                af[mt][2] = __float_as_uint(lo.y);
                af[mt][3] = __float_as_uint(hi.y);
            }
            #pragma unroll
            for (int nt = 0; nt < 8; nt++) {
                const int c = wn * 64 + nt * 8 + qr;
                float2 fb = *(const float2*)&Bs[cur][c * SA + kc];
                uint32_t b0 = __float_as_uint(fb.x), b1 = __float_as_uint(fb.y);
                #pragma unroll
                for (int mt = 0; mt < 4; mt++)
                    mma_tf32_16x8x8(acc[mt][nt][0], acc[mt][nt][1],
                                    acc[mt][nt][2], acc[mt][nt][3],
                                    af[mt][0], af[mt][1], af[mt][2], af[mt][3], b0, b1);
            }
        }
        if (kt + 1 < KT) {
            const int nxt = cur ^ 1;
            COMMIT(nxt);
            __syncthreads();
        }
    }
    #undef COMMIT

    // epilogue
    #pragma unroll
    for (int mt = 0; mt < 4; mt++) {
        const int r0 = bm + wm * 64 + mt * 16 + qr;
        #pragma unroll
        for (int nt = 0; nt < 8; nt++) {
            const int c0 = bn + wn * 64 + nt * 8 + qc * 2;
            if (c0 + 1 < N) {
                *(float2*)(C + (size_t)r0 * ldc + c0) =
                    make_float2(acc[mt][nt][0], acc[mt][nt][1]);
                *(float2*)(C + (size_t)(r0 + 8) * ldc + c0) =
                    make_float2(acc[mt][nt][2], acc[mt][nt][3]);
            } else if (c0 < N) {
                C[(size_t)r0 * ldc + c0] = acc[mt][nt][0];
                C[(size_t)(r0 + 8) * ldc + c0] = acc[mt][nt][2];
            }
        }
    }
}

// ---------------- embed ----------------
__global__ void k_embed(const float* __restrict__ coords,
                        const float* __restrict__ emb_W,
                        const float* __restrict__ emb_b) {
    int id = blockIdx.x * blockDim.x + threadIdx.x;
    if (id >= NT * DM) return;
    int d = id % DM, t = id / DM;
    float c0 = coords[t * 2 + 0], c1 = coords[t * 2 + 1];
    g_x[id] = c0 * emb_W[d * 2 + 0] + c1 * emb_W[d * 2 + 1] + emb_b[d];
}

// ---------------- residual add + layernorm ----------------
__global__ void k_ln(const float* __restrict__ w, const float* __restrict__ b, int layer) {
    int t = blockIdx.x;
    int d = threadIdx.x;
    float xv = g_x[t * DM + d];
    float rv = (layer == 0) ? xv : xv + g_res[t * DM + d];
    g_res[t * DM + d] = rv;

    float s = rv, s2 = rv * rv;
    #pragma unroll
    for (int o = 16; o; o >>= 1) {
        s  += __shfl_xor_sync(0xFFFFFFFFu, s,  o);
        s2 += __shfl_xor_sync(0xFFFFFFFFu, s2, o);
    }
    __shared__ float sh1[8], sh2[8];
    if ((d & 31) == 0) { sh1[d >> 5] = s; sh2[d >> 5] = s2; }
    __syncthreads();
    float ts = 0.f, ts2 = 0.f;
    #pragma unroll
    for (int i = 0; i < 8; i++) { ts += sh1[i]; ts2 += sh2[i]; }
    float mean = ts * (1.0f / DM);
    float var  = ts2 * (1.0f / DM) - mean * mean;
    float inv  = rsqrtf(var + EPSL);
    g_h[t * DM + d] = (rv - mean) * inv * w[layer * DM + d] + b[layer * DM + d];
}

// ---------------- causal depthwise conv (k=4) + silu ----------------
__global__ void k_conv(const float* __restrict__ cw, const float* __restrict__ cb, int layer) {
    int id = blockIdx.x * blockDim.x + threadIdx.x;
    if (id >= NT * DI) return;
    int d = id % DI, t = id / DI;
    int l = t % LEN, base = t - l;
    float4 wv = *(const float4*)(cw + (size_t)(layer * DI + d) * 4);
    float acc = cb[layer * DI + d];
    const float* src = g_xz + (size_t)base * (2 * DI) + d;
    if (l >= 3) {
        const float* p = src + (size_t)(l - 3) * (2 * DI);
        acc += p[0] * wv.x;
        acc += p[2 * DI] * wv.y;
        acc += p[4 * DI] * wv.z;
        acc += p[6 * DI] * wv.w;
    } else {
        const float w4[4] = {wv.x, wv.y, wv.z, wv.w};
        #pragma unroll
        for (int k = 0; k < 4; k++) {
            int ls = l - 3 + k;
            if (ls >= 0) acc += src[(size_t)ls * (2 * DI)] * w4[k];
        }
    }
    g_xc[id] = acc / (1.f + __expf(-acc));
}

// ------- selective scan, fused dt_proj+softplus, software-pipelined -------
__global__ __launch_bounds__(128) void k_scan3(
        const float* __restrict__ A_log, const float* __restrict__ D_skip,
        const float* __restrict__ dtW_all, const float* __restrict__ dtb_all,
        int layer) {
    int id = blockIdx.x * blockDim.x + threadIdx.x;   // 2*BATCH*DI = 32768
    if (id >= 2 * BATCH * DI) return;
    const int half = id & 1;
    const int d = (id >> 1) % DI;
    const int b = id >> 10;
    const int s0 = half * 8;

    const float* wp = dtW_all + (size_t)(layer * DI + d) * DR;
    float4 w0 = *(const float4*)(wp);
    float4 w1 = *(const float4*)(wp + 4);
    float4 w2 = *(const float4*)(wp + 8);
    float4 w3 = *(const float4*)(wp + 12);
    const float dtb = dtb_all[layer * DI + d];

    float An[8];
    #pragma unroll
    for (int s = 0; s < 8; s++)
        An[s] = -__expf(A_log[(size_t)(layer * DI + d) * DS + s0 + s]);
    const float Dv = D_skip[layer * DI + d];

    float h[8];
    #pragma unroll
    for (int s = 0; s < 8; s++) h[s] = 0.f;

    int t = b * LEN;
    const float* dp = g_dbl + (size_t)t * 48;
    float  xv_n = g_xc[(size_t)t * DI + d];
    float  zv_n = g_xz[(size_t)t * (2 * DI) + DI + d];
    float4 r0n = *(const float4*)(dp);
    float4 r1n = *(const float4*)(dp + 4);
    float4 r2n = *(const float4*)(dp + 8);
    float4 r3n = *(const float4*)(dp + 12);
    float4 bBn0 = *(const float4*)(dp + 16 + s0);
    float4 bBn1 = *(const float4*)(dp + 20 + s0);
    float4 bCn0 = *(const float4*)(dp + 32 + s0);
    float4 bCn1 = *(const float4*)(dp + 36 + s0);

    for (int l = 0; l < LEN; l++, t++) {
        const float  xv = xv_n, zv = zv_n;
        const float4 r0 = r0n, r1 = r1n, r2 = r2n, r3 = r3n;
        const float4 bB0 = bBn0, bB1 = bBn1, bC0 = bCn0, bC1 = bCn1;

        if (l + 1 < LEN) {
            const float* dq = g_dbl + (size_t)(t + 1) * 48;
            xv_n = g_xc[(size_t)(t + 1) * DI + d];
            zv_n = g_xz[(size_t)(t + 1) * (2 * DI) + DI + d];
            r0n = *(const float4*)(dq);
            r1n = *(const float4*)(dq + 4);
            r2n = *(const float4*)(dq + 8);
            r3n = *(const float4*)(dq + 12);
            bBn0 = *(const float4*)(dq + 16 + s0);
            bBn1 = *(const float4*)(dq + 20 + s0);
            bCn0 = *(const float4*)(dq + 32 + s0);
            bCn1 = *(const float4*)(dq + 36 + s0);
        }

        float a = dtb;
        a += r0.x * w0.x + r0.y * w0.y + r0.z * w0.z + r0.w * w0.w;
        a += r1.x * w1.x + r1.y * w1.y + r1.z * w1.z + r1.w * w1.w;
        a += r2.x * w2.x + r2.y * w2.y + r2.z * w2.z + r2.w * w2.w;
        a += r3.x * w3.x + r3.y * w3.y + r3.z * w3.z + r3.w * w3.w;
        const float dtv = (a > 20.f) ? a : log1pf(__expf(a));
        const float dx = dtv * xv;

        const float Bv[8] = {bB0.x, bB0.y, bB0.z, bB0.w, bB1.x, bB1.y, bB1.z, bB1.w};
        const float Cv[8] = {bC0.x, bC0.y, bC0.z, bC0.w, bC1.x, bC1.y, bC1.z, bC1.w};
        float y = 0.f;
        #pragma unroll
        for (int s = 0; s < 8; s++) {
            float da = __expf(dtv * An[s]);
            float hv = da * h[s] + dx * Bv[s];
            h[s] = hv;
            y += hv * Cv[s];
        }
        y += __shfl_xor_sync(0xFFFFFFFFu, y, 1);
        if (half == 0) {
            float sz = zv / (1.f + __expf(-zv));
            g_y[(size_t)t * DI + d] = (y + xv * Dv) * sz;
        }
    }
}

// ---------------- final: residual add + RMSNorm ----------------
__global__ void k_final(const float* __restrict__ nw, const float* __restrict__ nb) {
    int t = blockIdx.x;
    int d = threadIdx.x;
    float rv = g_x[t * DM + d] + g_res[t * DM + d];
    float s2 = rv * rv;
    #pragma unroll
    for (int o = 16; o; o >>= 1) s2 += __shfl_xor_sync(0xFFFFFFFFu, s2, o);
    __shared__ float sh[8];
    if ((d & 31) == 0) sh[d >> 5] = s2;
    __syncthreads();
    float ts = 0.f;
    #pragma unroll
    for (int i = 0; i < 8; i++) ts += sh[i];
    float inv = rsqrtf(ts * (1.0f / DM) + EPSL);
    g_o[t * DM + d] = rv * inv * nw[d] + nb[d];
}

// ---------------- host launcher ----------------
extern "C" void kernel_launch(void* const* d_in, const int* in_sizes, int n_in,
                              void* d_out, int out_size) {
    const float* coords   = (const float*)d_in[0];
    const float* emb_W    = (const float*)d_in[1];
    const float* emb_b    = (const float*)d_in[2];
    const float* ln_w     = (const float*)d_in[3];
    const float* ln_b     = (const float*)d_in[4];
    const float* in_W     = (const float*)d_in[5];
    const float* conv_W   = (const float*)d_in[6];
    const float* conv_b   = (const float*)d_in[7];
    const float* xproj_W  = (const float*)d_in[8];
    const float* dtproj_W = (const float*)d_in[9];
    const float* dtproj_b = (const float*)d_in[10];
    const float* A_log    = (const float*)d_in[11];
    const float* D_skip   = (const float*)d_in[12];
    const float* out_W    = (const float*)d_in[13];
    const float* normf_w  = (const float*)d_in[14];
    const float* normf_b  = (const float*)d_in[15];
    const float* head_W   = (const float*)d_in[16];
    float* logits = (float*)d_out;

    float *ph, *pxz, *pxc, *pdbl, *py, *px, *po;
    cudaGetSymbolAddress((void**)&ph,   g_h);
    cudaGetSymbolAddress((void**)&pxz,  g_xz);
    cudaGetSymbolAddress((void**)&pxc,  g_xc);
    cudaGetSymbolAddress((void**)&pdbl, g_dbl);
    cudaGetSymbolAddress((void**)&py,   g_y);
    cudaGetSymbolAddress((void**)&px,   g_x);
    cudaGetSymbolAddress((void**)&po,   g_o);

    k_embed<<<(NT * DM + 255) / 256, 256>>>(coords, emb_W, emb_b);

    for (int layer = 0; layer < NL; layer++) {
        k_ln<<<NT, DM>>>(ln_w, ln_b, layer);
        // in_proj: (9600,256)x(1024,256)^T
        mmagemm<<<dim3(1024 / 128, NT / 128), 128>>>(
            ph, DM, in_W + (size_t)layer * 2 * DI * DM, pxz, 2 * DI, DM, 2 * DI);
        k_conv<<<(NT * DI + 255) / 256, 256>>>(conv_W, conv_b, layer);
        // x_proj: (9600,512)x(48,512)^T
        mmagemm<<<dim3(1, NT / 128), 128>>>(
            pxc, DI, xproj_W + (size_t)layer * 48 * DI, pdbl, 48, DI, 48);
        // fused dt_proj + softplus + scan + D-skip + silu gate
        k_scan3<<<2 * BATCH * DI / 128, 128>>>(A_log, D_skip, dtproj_W, dtproj_b, layer);
        // out_proj: (9600,512)x(256,512)^T
        mmagemm<<<dim3(DM / 128, NT / 128), 128>>>(
            py, DI, out_W + (size_t)layer * DM * DI, px, DM, DI, DM);
    }

    k_final<<<NT, DM>>>(normf_w, normf_b);
    // head: (9600,256)x(300,256)^T
    mmagemm<<<dim3(3, NT / 128), 128>>>(
        po, DM, head_W, logits, 300, DM, 300);
}

// round 11
// speedup vs baseline: 1.0646x; 1.0646x over previous
#include <cuda_runtime.h>
#include <math.h>
#include <stdint.h>

#define BATCH 32
#define LEN   300
#define DM    256
#define DI    512
#define DS    16
#define DR    16
#define NL    4
#define NT    (BATCH * LEN)   // 9600
#define EPSL  1e-5f

// ---------------- scratch ----------------
__device__ float g_x  [NT * DM];
__device__ float g_res[NT * DM];
__device__ float g_h  [NT * DM];
__device__ float g_xz [NT * 2 * DI];
__device__ float g_xc [NT * DI];
__device__ float g_dbl[NT * 48];
__device__ float g_y  [NT * DI];
__device__ float g_o  [NT * DM];

// ---------------- tf32 helpers ----------------
__device__ __forceinline__ float to_tf32(float x) {
    float r;
    asm("cvt.rna.tf32.f32 %0, %1;" : "=f"(r) : "f"(x));
    return r;
}
__device__ __forceinline__ void mma_tf32_16x8x8(
        float& d0, float& d1, float& d2, float& d3,
        uint32_t a0, uint32_t a1, uint32_t a2, uint32_t a3,
        uint32_t b0, uint32_t b1) {
    asm volatile(
        "mma.sync.aligned.m16n8k8.row.col.f32.tf32.tf32.f32 "
        "{%0,%1,%2,%3}, {%4,%5,%6,%7}, {%8,%9}, {%0,%1,%2,%3};"
        : "+f"(d0), "+f"(d1), "+f"(d2), "+f"(d3)
        : "r"(a0), "r"(a1), "r"(a2), "r"(a3), "r"(b0), "r"(b1));
}

// ================ TF32 tensor-core GEMM, double-buffered ================
// BM=128, BN=128, BK=16, 256 threads (8 warps: 4M x 2N), warp tile 32x64.
// Smem row stride 20: (20*qr + qc) mod 32 hits all banks. One sync per k-tile.
#define SA 20
__global__ __launch_bounds__(256, 2) void mmagemm(
        const float* __restrict__ A, int lda,
        const float* __restrict__ Bw,
        float* __restrict__ C, int N, int K, int ldc) {
    __shared__ float As[2][128 * SA];
    __shared__ float Bs[2][128 * SA];

    const int tid  = threadIdx.x;
    const int lane = tid & 31;
    const int wid  = tid >> 5;
    const int wm   = wid >> 1;
    const int wn   = wid & 1;
    const int bm   = blockIdx.y * 128;
    const int bn   = blockIdx.x * 128;

    const int trow = tid >> 1, tcol = (tid & 1) * 8;
    const bool bok = (bn + trow) < N;

    const float* Ag = A + (size_t)(bm + trow) * lda + tcol;
    const float* Bg = Bw + (size_t)(bn + trow) * K + tcol;

    float acc[2][8][4];
    #pragma unroll
    for (int mt = 0; mt < 2; mt++)
        #pragma unroll
        for (int nt = 0; nt < 8; nt++)
            #pragma unroll
            for (int e = 0; e < 4; e++) acc[mt][nt][e] = 0.f;

    float4 ra0 = *(const float4*)(Ag);
    float4 ra1 = *(const float4*)(Ag + 4);
    float4 rb0 = make_float4(0.f,0.f,0.f,0.f), rb1 = rb0;
    if (bok) { rb0 = *(const float4*)(Bg); rb1 = *(const float4*)(Bg + 4); }

    // commit stage 0
    {
        float* as = As[0] + trow * SA + tcol;
        float* bs = Bs[0] + trow * SA + tcol;
        as[0]=to_tf32(ra0.x); as[1]=to_tf32(ra0.y); as[2]=to_tf32(ra0.z); as[3]=to_tf32(ra0.w);
        as[4]=to_tf32(ra1.x); as[5]=to_tf32(ra1.y); as[6]=to_tf32(ra1.z); as[7]=to_tf32(ra1.w);
        bs[0]=to_tf32(rb0.x); bs[1]=to_tf32(rb0.y); bs[2]=to_tf32(rb0.z); bs[3]=to_tf32(rb0.w);
        bs[4]=to_tf32(rb1.x); bs[5]=to_tf32(rb1.y); bs[6]=to_tf32(rb1.z); bs[7]=to_tf32(rb1.w);
    }
    __syncthreads();

    const int qr = lane >> 2, qc = lane & 3;
    const int KT = K >> 4;
    for (int kt = 0; kt < KT; kt++) {
        const int cur = kt & 1;
        if (kt + 1 < KT) {
            const int off = (kt + 1) * 16;
            ra0 = *(const float4*)(Ag + off);
            ra1 = *(const float4*)(Ag + off + 4);
            if (bok) { rb0 = *(const float4*)(Bg + off); rb1 = *(const float4*)(Bg + off + 4); }
        }
        #pragma unroll
        for (int ks = 0; ks < 2; ks++) {
            const int k0 = ks * 8;
            uint32_t af[2][4];
            #pragma unroll
            for (int mt = 0; mt < 2; mt++) {
                const int r = wm * 32 + mt * 16 + qr;
                af[mt][0] = __float_as_uint(As[cur][(r    ) * SA + k0 + qc    ]);
                af[mt][1] = __float_as_uint(As[cur][(r + 8) * SA + k0 + qc    ]);
                af[mt][2] = __float_as_uint(As[cur][(r    ) * SA + k0 + qc + 4]);
                af[mt][3] = __float_as_uint(As[cur][(r + 8) * SA + k0 + qc + 4]);
            }
            #pragma unroll
            for (int nt = 0; nt < 8; nt++) {
                const int c = wn * 64 + nt * 8 + qr;
                uint32_t b0 = __float_as_uint(Bs[cur][c * SA + k0 + qc    ]);
                uint32_t b1 = __float_as_uint(Bs[cur][c * SA + k0 + qc + 4]);
                mma_tf32_16x8x8(acc[0][nt][0], acc[0][nt][1], acc[0][nt][2], acc[0][nt][3],
                                af[0][0], af[0][1], af[0][2], af[0][3], b0, b1);
                mma_tf32_16x8x8(acc[1][nt][0], acc[1][nt][1], acc[1][nt][2], acc[1][nt][3],
                                af[1][0], af[1][1], af[1][2], af[1][3], b0, b1);
            }
        }
        if (kt + 1 < KT) {
            const int nxt = cur ^ 1;
            float* as = As[nxt] + trow * SA + tcol;
            float* bs = Bs[nxt] + trow * SA + tcol;
            as[0]=to_tf32(ra0.x); as[1]=to_tf32(ra0.y); as[2]=to_tf32(ra0.z); as[3]=to_tf32(ra0.w);
            as[4]=to_tf32(ra1.x); as[5]=to_tf32(ra1.y); as[6]=to_tf32(ra1.z); as[7]=to_tf32(ra1.w);
            bs[0]=to_tf32(rb0.x); bs[1]=to_tf32(rb0.y); bs[2]=to_tf32(rb0.z); bs[3]=to_tf32(rb0.w);
            bs[4]=to_tf32(rb1.x); bs[5]=to_tf32(rb1.y); bs[6]=to_tf32(rb1.z); bs[7]=to_tf32(rb1.w);
            __syncthreads();
        }
    }

    #pragma unroll
    for (int mt = 0; mt < 2; mt++) {
        const int r0 = bm + wm * 32 + mt * 16 + qr;
        #pragma unroll
        for (int nt = 0; nt < 8; nt++) {
            const int c0 = bn + wn * 64 + nt * 8 + qc * 2;
            if (c0 + 1 < N) {
                *(float2*)(C + (size_t)r0 * ldc + c0) =
                    make_float2(acc[mt][nt][0], acc[mt][nt][1]);
                *(float2*)(C + (size_t)(r0 + 8) * ldc + c0) =
                    make_float2(acc[mt][nt][2], acc[mt][nt][3]);
            } else if (c0 < N) {
                C[(size_t)r0 * ldc + c0] = acc[mt][nt][0];
                C[(size_t)(r0 + 8) * ldc + c0] = acc[mt][nt][2];
            }
        }
    }
}

// ---------------- embed ----------------
__global__ void k_embed(const float* __restrict__ coords,
                        const float* __restrict__ emb_W,
                        const float* __restrict__ emb_b) {
    int id = blockIdx.x * blockDim.x + threadIdx.x;
    if (id >= NT * DM) return;
    int d = id % DM, t = id / DM;
    float c0 = coords[t * 2 + 0], c1 = coords[t * 2 + 1];
    g_x[id] = c0 * emb_W[d * 2 + 0] + c1 * emb_W[d * 2 + 1] + emb_b[d];
}

// ---------------- residual add + layernorm ----------------
__global__ void k_ln(const float* __restrict__ w, const float* __restrict__ b, int layer) {
    int t = blockIdx.x;
    int d = threadIdx.x;
    float xv = g_x[t * DM + d];
    float rv = (layer == 0) ? xv : xv + g_res[t * DM + d];
    g_res[t * DM + d] = rv;

    float s = rv, s2 = rv * rv;
    #pragma unroll
    for (int o = 16; o; o >>= 1) {
        s  += __shfl_xor_sync(0xFFFFFFFFu, s,  o);
        s2 += __shfl_xor_sync(0xFFFFFFFFu, s2, o);
    }
    __shared__ float sh1[8], sh2[8];
    if ((d & 31) == 0) { sh1[d >> 5] = s; sh2[d >> 5] = s2; }
    __syncthreads();
    float ts = 0.f, ts2 = 0.f;
    #pragma unroll
    for (int i = 0; i < 8; i++) { ts += sh1[i]; ts2 += sh2[i]; }
    float mean = ts * (1.0f / DM);
    float var  = ts2 * (1.0f / DM) - mean * mean;
    float inv  = rsqrtf(var + EPSL);
    g_h[t * DM + d] = (rv - mean) * inv * w[layer * DM + d] + b[layer * DM + d];
}

// ---------------- causal depthwise conv (k=4) + silu ----------------
__global__ void k_conv(const float* __restrict__ cw, const float* __restrict__ cb, int layer) {
    int id = blockIdx.x * blockDim.x + threadIdx.x;
    if (id >= NT * DI) return;
    int d = id % DI, t = id / DI;
    int l = t % LEN, base = t - l;
    float4 wv = *(const float4*)(cw + (size_t)(layer * DI + d) * 4);
    float acc = cb[layer * DI + d];
    const float* src = g_xz + (size_t)base * (2 * DI) + d;
    if (l >= 3) {
        const float* p = src + (size_t)(l - 3) * (2 * DI);
        acc += p[0] * wv.x;
        acc += p[2 * DI] * wv.y;
        acc += p[4 * DI] * wv.z;
        acc += p[6 * DI] * wv.w;
    } else {
        const float w4[4] = {wv.x, wv.y, wv.z, wv.w};
        #pragma unroll
        for (int k = 0; k < 4; k++) {
            int ls = l - 3 + k;
            if (ls >= 0) acc += src[(size_t)ls * (2 * DI)] * w4[k];
        }
    }
    g_xc[id] = acc / (1.f + __expf(-acc));
}

// ------- selective scan, fused dt_proj+softplus, software-pipelined -------
__global__ __launch_bounds__(128) void k_scan3(
        const float* __restrict__ A_log, const float* __restrict__ D_skip,
        const float* __restrict__ dtW_all, const float* __restrict__ dtb_all,
        int layer) {
    int id = blockIdx.x * blockDim.x + threadIdx.x;   // 2*BATCH*DI = 32768
    if (id >= 2 * BATCH * DI) return;
    const int half = id & 1;
    const int d = (id >> 1) % DI;
    const int b = id >> 10;
    const int s0 = half * 8;

    const float* wp = dtW_all + (size_t)(layer * DI + d) * DR;
    float4 w0 = *(const float4*)(wp);
    float4 w1 = *(const float4*)(wp + 4);
    float4 w2 = *(const float4*)(wp + 8);
    float4 w3 = *(const float4*)(wp + 12);
    const float dtb = dtb_all[layer * DI + d];

    float An[8];
    #pragma unroll
    for (int s = 0; s < 8; s++)
        An[s] = -__expf(A_log[(size_t)(layer * DI + d) * DS + s0 + s]);
    const float Dv = D_skip[layer * DI + d];

    float h[8];
    #pragma unroll
    for (int s = 0; s < 8; s++) h[s] = 0.f;

    int t = b * LEN;
    const float* dp = g_dbl + (size_t)t * 48;
    float  xv_n = g_xc[(size_t)t * DI + d];
    float  zv_n = g_xz[(size_t)t * (2 * DI) + DI + d];
    float4 r0n = *(const float4*)(dp);
    float4 r1n = *(const float4*)(dp + 4);
    float4 r2n = *(const float4*)(dp + 8);
    float4 r3n = *(const float4*)(dp + 12);
    float4 bBn0 = *(const float4*)(dp + 16 + s0);
    float4 bBn1 = *(const float4*)(dp + 20 + s0);
    float4 bCn0 = *(const float4*)(dp + 32 + s0);
    float4 bCn1 = *(const float4*)(dp + 36 + s0);

    for (int l = 0; l < LEN; l++, t++) {
        const float  xv = xv_n, zv = zv_n;
        const float4 r0 = r0n, r1 = r1n, r2 = r2n, r3 = r3n;
        const float4 bB0 = bBn0, bB1 = bBn1, bC0 = bCn0, bC1 = bCn1;

        if (l + 1 < LEN) {
            const float* dq = g_dbl + (size_t)(t + 1) * 48;
            xv_n = g_xc[(size_t)(t + 1) * DI + d];
            zv_n = g_xz[(size_t)(t + 1) * (2 * DI) + DI + d];
            r0n = *(const float4*)(dq);
            r1n = *(const float4*)(dq + 4);
            r2n = *(const float4*)(dq + 8);
            r3n = *(const float4*)(dq + 12);
            bBn0 = *(const float4*)(dq + 16 + s0);
            bBn1 = *(const float4*)(dq + 20 + s0);
            bCn0 = *(const float4*)(dq + 32 + s0);
            bCn1 = *(const float4*)(dq + 36 + s0);
        }

        float a = dtb;
        a += r0.x * w0.x + r0.y * w0.y + r0.z * w0.z + r0.w * w0.w;
        a += r1.x * w1.x + r1.y * w1.y + r1.z * w1.z + r1.w * w1.w;
        a += r2.x * w2.x + r2.y * w2.y + r2.z * w2.z + r2.w * w2.w;
        a += r3.x * w3.x + r3.y * w3.y + r3.z * w3.z + r3.w * w3.w;
        const float dtv = (a > 20.f) ? a : log1pf(__expf(a));
        const float dx = dtv * xv;

        const float Bv[8] = {bB0.x, bB0.y, bB0.z, bB0.w, bB1.x, bB1.y, bB1.z, bB1.w};
        const float Cv[8] = {bC0.x, bC0.y, bC0.z, bC0.w, bC1.x, bC1.y, bC1.z, bC1.w};
        float y = 0.f;
        #pragma unroll
        for (int s = 0; s < 8; s++) {
            float da = __expf(dtv * An[s]);
            float hv = da * h[s] + dx * Bv[s];
            h[s] = hv;
            y += hv * Cv[s];
        }
        y += __shfl_xor_sync(0xFFFFFFFFu, y, 1);
        if (half == 0) {
            float sz = zv / (1.f + __expf(-zv));
            g_y[(size_t)t * DI + d] = (y + xv * Dv) * sz;
        }
    }
}

// ---------------- final: residual add + RMSNorm ----------------
__global__ void k_final(const float* __restrict__ nw, const float* __restrict__ nb) {
    int t = blockIdx.x;
    int d = threadIdx.x;
    float rv = g_x[t * DM + d] + g_res[t * DM + d];
    float s2 = rv * rv;
    #pragma unroll
    for (int o = 16; o; o >>= 1) s2 += __shfl_xor_sync(0xFFFFFFFFu, s2, o);
    __shared__ float sh[8];
    if ((d & 31) == 0) sh[d >> 5] = s2;
    __syncthreads();
    float ts = 0.f;
    #pragma unroll
    for (int i = 0; i < 8; i++) ts += sh[i];
    float inv = rsqrtf(ts * (1.0f / DM) + EPSL);
    g_o[t * DM + d] = rv * inv * nw[d] + nb[d];
}

// ---------------- host launcher ----------------
extern "C" void kernel_launch(void* const* d_in, const int* in_sizes, int n_in,
                              void* d_out, int out_size) {
    const float* coords   = (const float*)d_in[0];
    const float* emb_W    = (const float*)d_in[1];
    const float* emb_b    = (const float*)d_in[2];
    const float* ln_w     = (const float*)d_in[3];
    const float* ln_b     = (const float*)d_in[4];
    const float* in_W     = (const float*)d_in[5];
    const float* conv_W   = (const float*)d_in[6];
    const float* conv_b   = (const float*)d_in[7];
    const float* xproj_W  = (const float*)d_in[8];
    const float* dtproj_W = (const float*)d_in[9];
    const float* dtproj_b = (const float*)d_in[10];
    const float* A_log    = (const float*)d_in[11];
    const float* D_skip   = (const float*)d_in[12];
    const float* out_W    = (const float*)d_in[13];
    const float* normf_w  = (const float*)d_in[14];
    const float* normf_b  = (const float*)d_in[15];
    const float* head_W   = (const float*)d_in[16];
    float* logits = (float*)d_out;

    float *ph, *pxz, *pxc, *pdbl, *py, *px, *po;
    cudaGetSymbolAddress((void**)&ph,   g_h);
    cudaGetSymbolAddress((void**)&pxz,  g_xz);
    cudaGetSymbolAddress((void**)&pxc,  g_xc);
    cudaGetSymbolAddress((void**)&pdbl, g_dbl);
    cudaGetSymbolAddress((void**)&py,   g_y);
    cudaGetSymbolAddress((void**)&px,   g_x);
    cudaGetSymbolAddress((void**)&po,   g_o);

    k_embed<<<(NT * DM + 255) / 256, 256>>>(coords, emb_W, emb_b);

    for (int layer = 0; layer < NL; layer++) {
        k_ln<<<NT, DM>>>(ln_w, ln_b, layer);
        // in_proj: (9600,256)x(1024,256)^T
        mmagemm<<<dim3(1024 / 128, NT / 128), 256>>>(
            ph, DM, in_W + (size_t)layer * 2 * DI * DM, pxz, 2 * DI, DM, 2 * DI);
        k_conv<<<(NT * DI + 255) / 256, 256>>>(conv_W, conv_b, layer);
        // x_proj: (9600,512)x(48,512)^T
        mmagemm<<<dim3(1, NT / 128), 256>>>(
            pxc, DI, xproj_W + (size_t)layer * 48 * DI, pdbl, 48, DI, 48);
        // fused dt_proj + softplus + scan + D-skip + silu gate
        k_scan3<<<2 * BATCH * DI / 128, 128>>>(A_log, D_skip, dtproj_W, dtproj_b, layer);
        // out_proj: (9600,512)x(256,512)^T
        mmagemm<<<dim3(DM / 128, NT / 128), 256>>>(
            py, DI, out_W + (size_t)layer * DM * DI, px, DM, DI, DM);
    }

    k_final<<<NT, DM>>>(normf_w, normf_b);
    // head: (9600,256)x(300,256)^T
    mmagemm<<<dim3(3, NT / 128), 256>>>(
        po, DM, head_W, logits, 300, DM, 300);
}

// round 13
// speedup vs baseline: 1.0979x; 1.0313x over previous
#include <cuda_runtime.h>
#include <math.h>
#include <stdint.h>

#define BATCH 32
#define LEN   300
#define DM    256
#define DI    512
#define DS    16
#define DR    16
#define NL    4
#define NT    (BATCH * LEN)   // 9600
#define EPSL  1e-5f

// ---------------- scratch ----------------
__device__ float g_x  [NT * DM];
__device__ float g_res[NT * DM];
__device__ float g_h  [NT * DM];
__device__ float g_xz [NT * 2 * DI];
__device__ float g_xc [NT * DI];
__device__ float g_dbl[NT * 48];
__device__ float g_y  [NT * DI];
__device__ float g_o  [NT * DM];

// ---------------- tf32 helpers ----------------
__device__ __forceinline__ float to_tf32(float x) {
    float r;
    asm("cvt.rna.tf32.f32 %0, %1;" : "=f"(r) : "f"(x));
    return r;
}
__device__ __forceinline__ void mma_tf32_16x8x8(
        float& d0, float& d1, float& d2, float& d3,
        uint32_t a0, uint32_t a1, uint32_t a2, uint32_t a3,
        uint32_t b0, uint32_t b1) {
    asm volatile(
        "mma.sync.aligned.m16n8k8.row.col.f32.tf32.tf32.f32 "
        "{%0,%1,%2,%3}, {%4,%5,%6,%7}, {%8,%9}, {%0,%1,%2,%3};"
        : "+f"(d0), "+f"(d1), "+f"(d2), "+f"(d3)
        : "r"(a0), "r"(a1), "r"(a2), "r"(a3), "r"(b0), "r"(b1));
}

// ================ TF32 MMA GEMM, BM=128: double-buffered ================
// BM=128, BN=128, BK=16, 256 threads (8 warps: 4M x 2N), warp tile 32x64.
#define SA 20
__global__ __launch_bounds__(256, 2) void mmagemm(
        const float* __restrict__ A, int lda,
        const float* __restrict__ Bw,
        float* __restrict__ C, int N, int K, int ldc) {
    __shared__ float As[2][128 * SA];
    __shared__ float Bs[2][128 * SA];

    const int tid  = threadIdx.x;
    const int lane = tid & 31;
    const int wid  = tid >> 5;
    const int wm   = wid >> 1;
    const int wn   = wid & 1;
    const int bm   = blockIdx.y * 128;
    const int bn   = blockIdx.x * 128;

    const int trow = tid >> 1, tcol = (tid & 1) * 8;
    const bool bok = (bn + trow) < N;

    const float* Ag = A + (size_t)(bm + trow) * lda + tcol;
    const float* Bg = Bw + (size_t)(bn + trow) * K + tcol;

    float acc[2][8][4];
    #pragma unroll
    for (int mt = 0; mt < 2; mt++)
        #pragma unroll
        for (int nt = 0; nt < 8; nt++)
            #pragma unroll
            for (int e = 0; e < 4; e++) acc[mt][nt][e] = 0.f;

    float4 ra0 = *(const float4*)(Ag);
    float4 ra1 = *(const float4*)(Ag + 4);
    float4 rb0 = make_float4(0.f,0.f,0.f,0.f), rb1 = rb0;
    if (bok) { rb0 = *(const float4*)(Bg); rb1 = *(const float4*)(Bg + 4); }

    {
        float* as = As[0] + trow * SA + tcol;
        float* bs = Bs[0] + trow * SA + tcol;
        as[0]=to_tf32(ra0.x); as[1]=to_tf32(ra0.y); as[2]=to_tf32(ra0.z); as[3]=to_tf32(ra0.w);
        as[4]=to_tf32(ra1.x); as[5]=to_tf32(ra1.y); as[6]=to_tf32(ra1.z); as[7]=to_tf32(ra1.w);
        bs[0]=to_tf32(rb0.x); bs[1]=to_tf32(rb0.y); bs[2]=to_tf32(rb0.z); bs[3]=to_tf32(rb0.w);
        bs[4]=to_tf32(rb1.x); bs[5]=to_tf32(rb1.y); bs[6]=to_tf32(rb1.z); bs[7]=to_tf32(rb1.w);
    }
    __syncthreads();

    const int qr = lane >> 2, qc = lane & 3;
    const int KT = K >> 4;
    for (int kt = 0; kt < KT; kt++) {
        const int cur = kt & 1;
        if (kt + 1 < KT) {
            const int off = (kt + 1) * 16;
            ra0 = *(const float4*)(Ag + off);
            ra1 = *(const float4*)(Ag + off + 4);
            if (bok) { rb0 = *(const float4*)(Bg + off); rb1 = *(const float4*)(Bg + off + 4); }
        }
        #pragma unroll
        for (int ks = 0; ks < 2; ks++) {
            const int k0 = ks * 8;
            uint32_t af[2][4];
            #pragma unroll
            for (int mt = 0; mt < 2; mt++) {
                const int r = wm * 32 + mt * 16 + qr;
                af[mt][0] = __float_as_uint(As[cur][(r    ) * SA + k0 + qc    ]);
                af[mt][1] = __float_as_uint(As[cur][(r + 8) * SA + k0 + qc    ]);
                af[mt][2] = __float_as_uint(As[cur][(r    ) * SA + k0 + qc + 4]);
                af[mt][3] = __float_as_uint(As[cur][(r + 8) * SA + k0 + qc + 4]);
            }
            #pragma unroll
            for (int nt = 0; nt < 8; nt++) {
                const int c = wn * 64 + nt * 8 + qr;
                uint32_t b0 = __float_as_uint(Bs[cur][c * SA + k0 + qc    ]);
                uint32_t b1 = __float_as_uint(Bs[cur][c * SA + k0 + qc + 4]);
                mma_tf32_16x8x8(acc[0][nt][0], acc[0][nt][1], acc[0][nt][2], acc[0][nt][3],
                                af[0][0], af[0][1], af[0][2], af[0][3], b0, b1);
                mma_tf32_16x8x8(acc[1][nt][0], acc[1][nt][1], acc[1][nt][2], acc[1][nt][3],
                                af[1][0], af[1][1], af[1][2], af[1][3], b0, b1);
            }
        }
        if (kt + 1 < KT) {
            const int nxt = cur ^ 1;
            float* as = As[nxt] + trow * SA + tcol;
            float* bs = Bs[nxt] + trow * SA + tcol;
            as[0]=to_tf32(ra0.x); as[1]=to_tf32(ra0.y); as[2]=to_tf32(ra0.z); as[3]=to_tf32(ra0.w);
            as[4]=to_tf32(ra1.x); as[5]=to_tf32(ra1.y); as[6]=to_tf32(ra1.z); as[7]=to_tf32(ra1.w);
            bs[0]=to_tf32(rb0.x); bs[1]=to_tf32(rb0.y); bs[2]=to_tf32(rb0.z); bs[3]=to_tf32(rb0.w);
            bs[4]=to_tf32(rb1.x); bs[5]=to_tf32(rb1.y); bs[6]=to_tf32(rb1.z); bs[7]=to_tf32(rb1.w);
            __syncthreads();
        }
    }

    #pragma unroll
    for (int mt = 0; mt < 2; mt++) {
        const int r0 = bm + wm * 32 + mt * 16 + qr;
        #pragma unroll
        for (int nt = 0; nt < 8; nt++) {
            const int c0 = bn + wn * 64 + nt * 8 + qc * 2;
            if (c0 + 1 < N) {
                *(float2*)(C + (size_t)r0 * ldc + c0) =
                    make_float2(acc[mt][nt][0], acc[mt][nt][1]);
                *(float2*)(C + (size_t)(r0 + 8) * ldc + c0) =
                    make_float2(acc[mt][nt][2], acc[mt][nt][3]);
            } else if (c0 < N) {
                C[(size_t)r0 * ldc + c0] = acc[mt][nt][0];
                C[(size_t)(r0 + 8) * ldc + c0] = acc[mt][nt][2];
            }
        }
    }
}

// ================ TF32 MMA GEMM, BM=64 (high occupancy; for small-N/tall) ================
// BM=64, BN=128, BK=16, 256 threads (8 warps: 2M x 4N), warp tile 32x32.
__global__ __launch_bounds__(256, 3) void mmagemm64(
        const float* __restrict__ A, int lda,
        const float* __restrict__ Bw,
        float* __restrict__ C, int N, int K, int ldc) {
    __shared__ float As[2][64 * SA];
    __shared__ float Bs[2][128 * SA];

    const int tid  = threadIdx.x;
    const int lane = tid & 31;
    const int wid  = tid >> 5;
    const int wm   = wid >> 2;          // 0..1
    const int wn   = wid & 3;           // 0..3
    const int bm   = blockIdx.y * 64;
    const int bn   = blockIdx.x * 128;

    const int arow = tid >> 2, acol = (tid & 3) * 4;   // A: 64x16, 4 floats/thread
    const int brow = tid >> 1, bcol = (tid & 1) * 8;   // B: 128x16, 8 floats/thread
    const bool bok = (bn + brow) < N;

    const float* Ag = A + (size_t)(bm + arow) * lda + acol;
    const float* Bg = Bw + (size_t)(bn + brow) * K + bcol;

    float acc[2][4][4];
    #pragma unroll
    for (int mt = 0; mt < 2; mt++)
        #pragma unroll
        for (int nt = 0; nt < 4; nt++)
            #pragma unroll
            for (int e = 0; e < 4; e++) acc[mt][nt][e] = 0.f;

    float4 ra = *(const float4*)(Ag);
    float4 rb0 = make_float4(0.f,0.f,0.f,0.f), rb1 = rb0;
    if (bok) { rb0 = *(const float4*)(Bg); rb1 = *(const float4*)(Bg + 4); }

    {
        float* as = As[0] + arow * SA + acol;
        float* bs = Bs[0] + brow * SA + bcol;
        as[0]=to_tf32(ra.x); as[1]=to_tf32(ra.y); as[2]=to_tf32(ra.z); as[3]=to_tf32(ra.w);
        bs[0]=to_tf32(rb0.x); bs[1]=to_tf32(rb0.y); bs[2]=to_tf32(rb0.z); bs[3]=to_tf32(rb0.w);
        bs[4]=to_tf32(rb1.x); bs[5]=to_tf32(rb1.y); bs[6]=to_tf32(rb1.z); bs[7]=to_tf32(rb1.w);
    }
    __syncthreads();

    const int qr = lane >> 2, qc = lane & 3;
    const int KT = K >> 4;
    for (int kt = 0; kt < KT; kt++) {
        const int cur = kt & 1;
        if (kt + 1 < KT) {
            const int off = (kt + 1) * 16;
            ra = *(const float4*)(Ag + off);
            if (bok) { rb0 = *(const float4*)(Bg + off); rb1 = *(const float4*)(Bg + off + 4); }
        }
        #pragma unroll
        for (int ks = 0; ks < 2; ks++) {
            const int k0 = ks * 8;
            uint32_t af[2][4];
            #pragma unroll
            for (int mt = 0; mt < 2; mt++) {
                const int r = wm * 32 + mt * 16 + qr;
                af[mt][0] = __float_as_uint(As[cur][(r    ) * SA + k0 + qc    ]);
                af[mt][1] = __float_as_uint(As[cur][(r + 8) * SA + k0 + qc    ]);
                af[mt][2] = __float_as_uint(As[cur][(r    ) * SA + k0 + qc + 4]);
                af[mt][3] = __float_as_uint(As[cur][(r + 8) * SA + k0 + qc + 4]);
            }
            #pragma unroll
            for (int nt = 0; nt < 4; nt++) {
                const int c = wn * 32 + nt * 8 + qr;
                uint32_t b0 = __float_as_uint(Bs[cur][c * SA + k0 + qc    ]);
                uint32_t b1 = __float_as_uint(Bs[cur][c * SA + k0 + qc + 4]);
                mma_tf32_16x8x8(acc[0][nt][0], acc[0][nt][1], acc[0][nt][2], acc[0][nt][3],
                                af[0][0], af[0][1], af[0][2], af[0][3], b0, b1);
                mma_tf32_16x8x8(acc[1][nt][0], acc[1][nt][1], acc[1][nt][2], acc[1][nt][3],
                                af[1][0], af[1][1], af[1][2], af[1][3], b0, b1);
            }
        }
        if (kt + 1 < KT) {
            const int nxt = cur ^ 1;
            float* as = As[nxt] + arow * SA + acol;
            float* bs = Bs[nxt] + brow * SA + bcol;
            as[0]=to_tf32(ra.x); as[1]=to_tf32(ra.y); as[2]=to_tf32(ra.z); as[3]=to_tf32(ra.w);
            bs[0]=to_tf32(rb0.x); bs[1]=to_tf32(rb0.y); bs[2]=to_tf32(rb0.z); bs[3]=to_tf32(rb0.w);
            bs[4]=to_tf32(rb1.x); bs[5]=to_tf32(rb1.y); bs[6]=to_tf32(rb1.z); bs[7]=to_tf32(rb1.w);
            __syncthreads();
        }
    }

    #pragma unroll
    for (int mt = 0; mt < 2; mt++) {
        const int r0 = bm + wm * 32 + mt * 16 + qr;
        #pragma unroll
        for (int nt = 0; nt < 4; nt++) {
            const int c0 = bn + wn * 32 + nt * 8 + qc * 2;
            if (c0 + 1 < N) {
                *(float2*)(C + (size_t)r0 * ldc + c0) =
                    make_float2(acc[mt][nt][0], acc[mt][nt][1]);
                *(float2*)(C + (size_t)(r0 + 8) * ldc + c0) =
                    make_float2(acc[mt][nt][2], acc[mt][nt][3]);
            } else if (c0 < N) {
                C[(size_t)r0 * ldc + c0] = acc[mt][nt][0];
                C[(size_t)(r0 + 8) * ldc + c0] = acc[mt][nt][2];
            }
        }
    }
}

// ---------------- residual add + layernorm (layer 0: embed inline) ----------------
__global__ void k_ln(const float* __restrict__ w, const float* __restrict__ b,
                     const float* __restrict__ coords,
                     const float* __restrict__ emb_W, const float* __restrict__ emb_b,
                     int layer) {
    int t = blockIdx.x;
    int d = threadIdx.x;
    float rv;
    if (layer == 0) {
        float c0 = coords[t * 2 + 0], c1 = coords[t * 2 + 1];
        rv = c0 * emb_W[d * 2 + 0] + c1 * emb_W[d * 2 + 1] + emb_b[d];
    } else {
        rv = g_x[t * DM + d] + g_res[t * DM + d];
    }
    g_res[t * DM + d] = rv;

    float s = rv, s2 = rv * rv;
    #pragma unroll
    for (int o = 16; o; o >>= 1) {
        s  += __shfl_xor_sync(0xFFFFFFFFu, s,  o);
        s2 += __shfl_xor_sync(0xFFFFFFFFu, s2, o);
    }
    __shared__ float sh1[8], sh2[8];
    if ((d & 31) == 0) { sh1[d >> 5] = s; sh2[d >> 5] = s2; }
    __syncthreads();
    float ts = 0.f, ts2 = 0.f;
    #pragma unroll
    for (int i = 0; i < 8; i++) { ts += sh1[i]; ts2 += sh2[i]; }
    float mean = ts * (1.0f / DM);
    float var  = ts2 * (1.0f / DM) - mean * mean;
    float inv  = rsqrtf(var + EPSL);
    g_h[t * DM + d] = (rv - mean) * inv * w[layer * DM + d] + b[layer * DM + d];
}

// ---------------- causal depthwise conv (k=4) + silu ----------------
__global__ void k_conv(const float* __restrict__ cw, const float* __restrict__ cb, int layer) {
    int id = blockIdx.x * blockDim.x + threadIdx.x;
    if (id >= NT * DI) return;
    int d = id % DI, t = id / DI;
    int l = t % LEN, base = t - l;
    float4 wv = *(const float4*)(cw + (size_t)(layer * DI + d) * 4);
    float acc = cb[layer * DI + d];
    const float* src = g_xz + (size_t)base * (2 * DI) + d;
    if (l >= 3) {
        const float* p = src + (size_t)(l - 3) * (2 * DI);
        acc += p[0] * wv.x;
        acc += p[2 * DI] * wv.y;
        acc += p[4 * DI] * wv.z;
        acc += p[6 * DI] * wv.w;
    } else {
        const float w4[4] = {wv.x, wv.y, wv.z, wv.w};
        #pragma unroll
        for (int k = 0; k < 4; k++) {
            int ls = l - 3 + k;
            if (ls >= 0) acc += src[(size_t)ls * (2 * DI)] * w4[k];
        }
    }
    g_xc[id] = acc / (1.f + __expf(-acc));
}

// ------- selective scan, fused dt_proj+softplus, software-pipelined -------
__global__ __launch_bounds__(128) void k_scan3(
        const float* __restrict__ A_log, const float* __restrict__ D_skip,
        const float* __restrict__ dtW_all, const float* __restrict__ dtb_all,
        int layer) {
    int id = blockIdx.x * blockDim.x + threadIdx.x;   // 2*BATCH*DI = 32768
    if (id >= 2 * BATCH * DI) return;
    const int half = id & 1;
    const int d = (id >> 1) % DI;
    const int b = id >> 10;
    const int s0 = half * 8;

    const float* wp = dtW_all + (size_t)(layer * DI + d) * DR;
    float4 w0 = *(const float4*)(wp);
    float4 w1 = *(const float4*)(wp + 4);
    float4 w2 = *(const float4*)(wp + 8);
    float4 w3 = *(const float4*)(wp + 12);
    const float dtb = dtb_all[layer * DI + d];

    float An[8];
    #pragma unroll
    for (int s = 0; s < 8; s++)
        An[s] = -__expf(A_log[(size_t)(layer * DI + d) * DS + s0 + s]);
    const float Dv = D_skip[layer * DI + d];

    float h[8];
    #pragma unroll
    for (int s = 0; s < 8; s++) h[s] = 0.f;

    int t = b * LEN;
    const float* dp = g_dbl + (size_t)t * 48;
    float  xv_n = g_xc[(size_t)t * DI + d];
    float  zv_n = g_xz[(size_t)t * (2 * DI) + DI + d];
    float4 r0n = *(const float4*)(dp);
    float4 r1n = *(const float4*)(dp + 4);
    float4 r2n = *(const float4*)(dp + 8);
    float4 r3n = *(const float4*)(dp + 12);
    float4 bBn0 = *(const float4*)(dp + 16 + s0);
    float4 bBn1 = *(const float4*)(dp + 20 + s0);
    float4 bCn0 = *(const float4*)(dp + 32 + s0);
    float4 bCn1 = *(const float4*)(dp + 36 + s0);

    for (int l = 0; l < LEN; l++, t++) {
        const float  xv = xv_n, zv = zv_n;
        const float4 r0 = r0n, r1 = r1n, r2 = r2n, r3 = r3n;
        const float4 bB0 = bBn0, bB1 = bBn1, bC0 = bCn0, bC1 = bCn1;

        if (l + 1 < LEN) {
            const float* dq = g_dbl + (size_t)(t + 1) * 48;
            xv_n = g_xc[(size_t)(t + 1) * DI + d];
            zv_n = g_xz[(size_t)(t + 1) * (2 * DI) + DI + d];
            r0n = *(const float4*)(dq);
            r1n = *(const float4*)(dq + 4);
            r2n = *(const float4*)(dq + 8);
            r3n = *(const float4*)(dq + 12);
            bBn0 = *(const float4*)(dq + 16 + s0);
            bBn1 = *(const float4*)(dq + 20 + s0);
            bCn0 = *(const float4*)(dq + 32 + s0);
            bCn1 = *(const float4*)(dq + 36 + s0);
        }

        float a = dtb;
        a += r0.x * w0.x + r0.y * w0.y + r0.z * w0.z + r0.w * w0.w;
        a += r1.x * w1.x + r1.y * w1.y + r1.z * w1.z + r1.w * w1.w;
        a += r2.x * w2.x + r2.y * w2.y + r2.z * w2.z + r2.w * w2.w;
        a += r3.x * w3.x + r3.y * w3.y + r3.z * w3.z + r3.w * w3.w;
        const float dtv = (a > 20.f) ? a : __logf(1.f + __expf(a));
        const float dx = dtv * xv;

        const float Bv[8] = {bB0.x, bB0.y, bB0.z, bB0.w, bB1.x, bB1.y, bB1.z, bB1.w};
        const float Cv[8] = {bC0.x, bC0.y, bC0.z, bC0.w, bC1.x, bC1.y, bC1.z, bC1.w};
        float y = 0.f;
        #pragma unroll
        for (int s = 0; s < 8; s++) {
            float da = __expf(dtv * An[s]);
            float hv = da * h[s] + dx * Bv[s];
            h[s] = hv;
            y += hv * Cv[s];
        }
        y += __shfl_xor_sync(0xFFFFFFFFu, y, 1);
        if (half == 0) {
            float sz = zv / (1.f + __expf(-zv));
            g_y[(size_t)t * DI + d] = (y + xv * Dv) * sz;
        }
    }
}

// ---------------- final: residual add + RMSNorm ----------------
__global__ void k_final(const float* __restrict__ nw, const float* __restrict__ nb) {
    int t = blockIdx.x;
    int d = threadIdx.x;
    float rv = g_x[t * DM + d] + g_res[t * DM + d];
    float s2 = rv * rv;
    #pragma unroll
    for (int o = 16; o; o >>= 1) s2 += __shfl_xor_sync(0xFFFFFFFFu, s2, o);
    __shared__ float sh[8];
    if ((d & 31) == 0) sh[d >> 5] = s2;
    __syncthreads();
    float ts = 0.f;
    #pragma unroll
    for (int i = 0; i < 8; i++) ts += sh[i];
    float inv = rsqrtf(ts * (1.0f / DM) + EPSL);
    g_o[t * DM + d] = rv * inv * nw[d] + nb[d];
}

// ---------------- host launcher ----------------
extern "C" void kernel_launch(void* const* d_in, const int* in_sizes, int n_in,
                              void* d_out, int out_size) {
    const float* coords   = (const float*)d_in[0];
    const float* emb_W    = (const float*)d_in[1];
    const float* emb_b    = (const float*)d_in[2];
    const float* ln_w     = (const float*)d_in[3];
    const float* ln_b     = (const float*)d_in[4];
    const float* in_W     = (const float*)d_in[5];
    const float* conv_W   = (const float*)d_in[6];
    const float* conv_b   = (const float*)d_in[7];
    const float* xproj_W  = (const float*)d_in[8];
    const float* dtproj_W = (const float*)d_in[9];
    const float* dtproj_b = (const float*)d_in[10];
    const float* A_log    = (const float*)d_in[11];
    const float* D_skip   = (const float*)d_in[12];
    const float* out_W    = (const float*)d_in[13];
    const float* normf_w  = (const float*)d_in[14];
    const float* normf_b  = (const float*)d_in[15];
    const float* head_W   = (const float*)d_in[16];
    float* logits = (float*)d_out;

    float *ph, *pxz, *pxc, *pdbl, *py, *px, *po;
    cudaGetSymbolAddress((void**)&ph,   g_h);
    cudaGetSymbolAddress((void**)&pxz,  g_xz);
    cudaGetSymbolAddress((void**)&pxc,  g_xc);
    cudaGetSymbolAddress((void**)&pdbl, g_dbl);
    cudaGetSymbolAddress((void**)&py,   g_y);
    cudaGetSymbolAddress((void**)&px,   g_x);
    cudaGetSymbolAddress((void**)&po,   g_o);

    for (int layer = 0; layer < NL; layer++) {
        // residual add + layernorm (layer 0 computes the embedding inline)
        k_ln<<<NT, DM>>>(ln_w, ln_b, coords, emb_W, emb_b, layer);
        // in_proj: (9600,256)x(1024,256)^T
        mmagemm<<<dim3(1024 / 128, NT / 128), 256>>>(
            ph, DM, in_W + (size_t)layer * 2 * DI * DM, pxz, 2 * DI, DM, 2 * DI);
        k_conv<<<(NT * DI + 255) / 256, 256>>>(conv_W, conv_b, layer);
        // x_proj: (9600,512)x(48,512)^T — BM=64 kernel for 2x grid, 3 CTA/SM
        mmagemm64<<<dim3(1, NT / 64), 256>>>(
            pxc, DI, xproj_W + (size_t)layer * 48 * DI, pdbl, 48, DI, 48);
        // fused dt_proj + softplus + scan + D-skip + silu gate
        k_scan3<<<2 * BATCH * DI / 128, 128>>>(A_log, D_skip, dtproj_W, dtproj_b, layer);
        // out_proj: (9600,512)x(256,512)^T
        mmagemm<<<dim3(DM / 128, NT / 128), 256>>>(
            py, DI, out_W + (size_t)layer * DM * DI, px, DM, DI, DM);
    }

    k_final<<<NT, DM>>>(normf_w, normf_b);
    // head: (9600,256)x(300,256)^T
    mmagemm<<<dim3(3, NT / 128), 256>>>(
        po, DM, head_W, logits, 300, DM, 300);
}

// round 15
// speedup vs baseline: 1.1137x; 1.0144x over previous
#include <cuda_runtime.h>
#include <math.h>
#include <stdint.h>

#define BATCH 32
#define LEN   300
#define DM    256
#define DI    512
#define DS    16
#define DR    16
#define NL    4
#define NT    (BATCH * LEN)   // 9600
#define EPSL  1e-5f

// ---------------- scratch ----------------
__device__ float g_x  [NT * DM];
__device__ float g_res[NT * DM];
__device__ float g_h  [NT * DM];
__device__ float g_xz [NT * 2 * DI];
__device__ float g_xc [NT * DI];
__device__ float g_dbl[NT * 48];
__device__ float g_y  [NT * DI];
__device__ float g_o  [NT * DM];
// pre-rounded (tf32) weights
__device__ float g_winW [NL * 2 * DI * DM];
__device__ float g_wxpW [NL * 48 * DI];
__device__ float g_woutW[NL * DM * DI];
__device__ float g_whW  [300 * DM];

// ---------------- helpers ----------------
__device__ __forceinline__ float to_tf32(float x) {
    float r;
    asm("cvt.rna.tf32.f32 %0, %1;" : "=f"(r) : "f"(x));
    return r;
}
__device__ __forceinline__ uint32_t s2u(const void* p) {
    uint32_t a;
    asm("{ .reg .u64 t; cvta.to.shared.u64 t, %1; cvt.u32.u64 %0, t; }" : "=r"(a) : "l"(p));
    return a;
}
__device__ __forceinline__ void cp16(uint32_t dst, const void* src, int srcsz) {
    asm volatile("cp.async.cg.shared.global [%0], [%1], 16, %2;"
                 :: "r"(dst), "l"(src), "r"(srcsz) : "memory");
}
#define CP_COMMIT() asm volatile("cp.async.commit_group;" ::: "memory")
#define CP_WAIT0()  asm volatile("cp.async.wait_group 0;" ::: "memory")

__device__ __forceinline__ void mma_tf32_16x8x8(
        float& d0, float& d1, float& d2, float& d3,
        uint32_t a0, uint32_t a1, uint32_t a2, uint32_t a3,
        uint32_t b0, uint32_t b1) {
    asm volatile(
        "mma.sync.aligned.m16n8k8.row.col.f32.tf32.tf32.f32 "
        "{%0,%1,%2,%3}, {%4,%5,%6,%7}, {%8,%9}, {%0,%1,%2,%3};"
        : "+f"(d0), "+f"(d1), "+f"(d2), "+f"(d3)
        : "r"(a0), "r"(a1), "r"(a2), "r"(a3), "r"(b0), "r"(b1));
}

// ---------------- weight pre-round ----------------
__global__ void k_round(const float* __restrict__ src, float* __restrict__ dst, int n) {
    int i = blockIdx.x * blockDim.x + threadIdx.x;
    if (i < n) dst[i] = to_tf32(src[i]);
}

// ================ TF32 MMA GEMM, BM=128, cp.async double-buffered ================
// BM=128, BN=128, BK=16, 256 threads (8 warps: 4M x 2N), warp tile 32x64.
// Inputs must already be tf32-rounded. Smem row stride 20 (bank-balanced, 16B-aligned).
#define SA 20
__global__ __launch_bounds__(256, 2) void mmagemm(
        const float* __restrict__ A, int lda,
        const float* __restrict__ Bw,
        float* __restrict__ C, int N, int K, int ldc) {
    __shared__ float As[2][128 * SA];
    __shared__ float Bs[2][128 * SA];

    const int tid  = threadIdx.x;
    const int lane = tid & 31;
    const int wid  = tid >> 5;
    const int wm   = wid >> 1;
    const int wn   = wid & 1;
    const int bm   = blockIdx.y * 128;
    const int bn   = blockIdx.x * 128;

    const int trow = tid >> 1, tcol = (tid & 1) * 8;
    const int bsz  = ((bn + trow) < N) ? 16 : 0;

    const float* Ag = A + (size_t)(bm + trow) * lda + tcol;
    const float* Bg = Bw + (size_t)(bn + trow) * K + tcol;
    const uint32_t sAoff = (uint32_t)(trow * SA + tcol) * 4u;

    float acc[2][8][4];
    #pragma unroll
    for (int mt = 0; mt < 2; mt++)
        #pragma unroll
        for (int nt = 0; nt < 8; nt++)
            #pragma unroll
            for (int e = 0; e < 4; e++) acc[mt][nt][e] = 0.f;

    // stage 0
    {
        uint32_t da = s2u(As[0]) + sAoff;
        uint32_t db = s2u(Bs[0]) + sAoff;
        cp16(da, Ag, 16); cp16(da + 16, Ag + 4, 16);
        cp16(db, Bg, bsz); cp16(db + 16, Bg + 4, bsz);
        CP_COMMIT();
    }
    CP_WAIT0();
    __syncthreads();

    const int qr = lane >> 2, qc = lane & 3;
    const int KT = K >> 4;
    for (int kt = 0; kt < KT; kt++) {
        const int cur = kt & 1;
        if (kt + 1 < KT) {
            const int off = (kt + 1) * 16;
            uint32_t da = s2u(As[cur ^ 1]) + sAoff;
            uint32_t db = s2u(Bs[cur ^ 1]) + sAoff;
            cp16(da, Ag + off, 16); cp16(da + 16, Ag + off + 4, 16);
            cp16(db, Bg + off, bsz); cp16(db + 16, Bg + off + 4, bsz);
            CP_COMMIT();
        }
        #pragma unroll
        for (int ks = 0; ks < 2; ks++) {
            const int k0 = ks * 8;
            uint32_t af[2][4];
            #pragma unroll
            for (int mt = 0; mt < 2; mt++) {
                const int r = wm * 32 + mt * 16 + qr;
                af[mt][0] = __float_as_uint(As[cur][(r    ) * SA + k0 + qc    ]);
                af[mt][1] = __float_as_uint(As[cur][(r + 8) * SA + k0 + qc    ]);
                af[mt][2] = __float_as_uint(As[cur][(r    ) * SA + k0 + qc + 4]);
                af[mt][3] = __float_as_uint(As[cur][(r + 8) * SA + k0 + qc + 4]);
            }
            #pragma unroll
            for (int nt = 0; nt < 8; nt++) {
                const int c = wn * 64 + nt * 8 + qr;
                uint32_t b0 = __float_as_uint(Bs[cur][c * SA + k0 + qc    ]);
                uint32_t b1 = __float_as_uint(Bs[cur][c * SA + k0 + qc + 4]);
                mma_tf32_16x8x8(acc[0][nt][0], acc[0][nt][1], acc[0][nt][2], acc[0][nt][3],
                                af[0][0], af[0][1], af[0][2], af[0][3], b0, b1);
                mma_tf32_16x8x8(acc[1][nt][0], acc[1][nt][1], acc[1][nt][2], acc[1][nt][3],
                                af[1][0], af[1][1], af[1][2], af[1][3], b0, b1);
            }
        }
        if (kt + 1 < KT) {
            CP_WAIT0();
            __syncthreads();
        }
    }

    #pragma unroll
    for (int mt = 0; mt < 2; mt++) {
        const int r0 = bm + wm * 32 + mt * 16 + qr;
        #pragma unroll
        for (int nt = 0; nt < 8; nt++) {
            const int c0 = bn + wn * 64 + nt * 8 + qc * 2;
            if (c0 + 1 < N) {
                *(float2*)(C + (size_t)r0 * ldc + c0) =
                    make_float2(acc[mt][nt][0], acc[mt][nt][1]);
                *(float2*)(C + (size_t)(r0 + 8) * ldc + c0) =
                    make_float2(acc[mt][nt][2], acc[mt][nt][3]);
            } else if (c0 < N) {
                C[(size_t)r0 * ldc + c0] = acc[mt][nt][0];
                C[(size_t)(r0 + 8) * ldc + c0] = acc[mt][nt][2];
            }
        }
    }
}

// ================ TF32 MMA GEMM, BM=64, cp.async (high occupancy) ================
// BM=64, BN=128, BK=16, 256 threads (8 warps: 2M x 4N), warp tile 32x32.
__global__ __launch_bounds__(256, 3) void mmagemm64(
        const float* __restrict__ A, int lda,
        const float* __restrict__ Bw,
        float* __restrict__ C, int N, int K, int ldc) {
    __shared__ float As[2][64 * SA];
    __shared__ float Bs[2][128 * SA];

    const int tid  = threadIdx.x;
    const int lane = tid & 31;
    const int wid  = tid >> 5;
    const int wm   = wid >> 2;
    const int wn   = wid & 3;
    const int bm   = blockIdx.y * 64;
    const int bn   = blockIdx.x * 128;

    const int arow = tid >> 2, acol = (tid & 3) * 4;   // A: 64x16, 16B/thread
    const int brow = tid >> 1, bcol = (tid & 1) * 8;   // B: 128x16, 32B/thread
    const int bsz  = ((bn + brow) < N) ? 16 : 0;

    const float* Ag = A + (size_t)(bm + arow) * lda + acol;
    const float* Bg = Bw + (size_t)(bn + brow) * K + bcol;
    const uint32_t sAof = (uint32_t)(arow * SA + acol) * 4u;
    const uint32_t sBof = (uint32_t)(brow * SA + bcol) * 4u;

    float acc[2][4][4];
    #pragma unroll
    for (int mt = 0; mt < 2; mt++)
        #pragma unroll
        for (int nt = 0; nt < 4; nt++)
            #pragma unroll
            for (int e = 0; e < 4; e++) acc[mt][nt][e] = 0.f;

    {
        cp16(s2u(As[0]) + sAof, Ag, 16);
        uint32_t db = s2u(Bs[0]) + sBof;
        cp16(db, Bg, bsz); cp16(db + 16, Bg + 4, bsz);
        CP_COMMIT();
    }
    CP_WAIT0();
    __syncthreads();

    const int qr = lane >> 2, qc = lane & 3;
    const int KT = K >> 4;
    for (int kt = 0; kt < KT; kt++) {
        const int cur = kt & 1;
        if (kt + 1 < KT) {
            const int off = (kt + 1) * 16;
            cp16(s2u(As[cur ^ 1]) + sAof, Ag + off, 16);
            uint32_t db = s2u(Bs[cur ^ 1]) + sBof;
            cp16(db, Bg + off, bsz); cp16(db + 16, Bg + off + 4, bsz);
            CP_COMMIT();
        }
        #pragma unroll
        for (int ks = 0; ks < 2; ks++) {
            const int k0 = ks * 8;
            uint32_t af[2][4];
            #pragma unroll
            for (int mt = 0; mt < 2; mt++) {
                const int r = wm * 32 + mt * 16 + qr;
                af[mt][0] = __float_as_uint(As[cur][(r    ) * SA + k0 + qc    ]);
                af[mt][1] = __float_as_uint(As[cur][(r + 8) * SA + k0 + qc    ]);
                af[mt][2] = __float_as_uint(As[cur][(r    ) * SA + k0 + qc + 4]);
                af[mt][3] = __float_as_uint(As[cur][(r + 8) * SA + k0 + qc + 4]);
            }
            #pragma unroll
            for (int nt = 0; nt < 4; nt++) {
                const int c = wn * 32 + nt * 8 + qr;
                uint32_t b0 = __float_as_uint(Bs[cur][c * SA + k0 + qc    ]);
                uint32_t b1 = __float_as_uint(Bs[cur][c * SA + k0 + qc + 4]);
                mma_tf32_16x8x8(acc[0][nt][0], acc[0][nt][1], acc[0][nt][2], acc[0][nt][3],
                                af[0][0], af[0][1], af[0][2], af[0][3], b0, b1);
                mma_tf32_16x8x8(acc[1][nt][0], acc[1][nt][1], acc[1][nt][2], acc[1][nt][3],
                                af[1][0], af[1][1], af[1][2], af[1][3], b0, b1);
            }
        }
        if (kt + 1 < KT) {
            CP_WAIT0();
            __syncthreads();
        }
    }

    #pragma unroll
    for (int mt = 0; mt < 2; mt++) {
        const int r0 = bm + wm * 32 + mt * 16 + qr;
        #pragma unroll
        for (int nt = 0; nt < 4; nt++) {
            const int c0 = bn + wn * 32 + nt * 8 + qc * 2;
            if (c0 + 1 < N) {
                *(float2*)(C + (size_t)r0 * ldc + c0) =
                    make_float2(acc[mt][nt][0], acc[mt][nt][1]);
                *(float2*)(C + (size_t)(r0 + 8) * ldc + c0) =
                    make_float2(acc[mt][nt][2], acc[mt][nt][3]);
            } else if (c0 < N) {
                C[(size_t)r0 * ldc + c0] = acc[mt][nt][0];
                C[(size_t)(r0 + 8) * ldc + c0] = acc[mt][nt][2];
            }
        }
    }
}

// ---------------- residual add + layernorm (layer 0: embed inline) ----------------
__global__ void k_ln(const float* __restrict__ w, const float* __restrict__ b,
                     const float* __restrict__ coords,
                     const float* __restrict__ emb_W, const float* __restrict__ emb_b,
                     int layer) {
    int t = blockIdx.x;
    int d = threadIdx.x;
    float rv;
    if (layer == 0) {
        float c0 = coords[t * 2 + 0], c1 = coords[t * 2 + 1];
        rv = c0 * emb_W[d * 2 + 0] + c1 * emb_W[d * 2 + 1] + emb_b[d];
    } else {
        rv = g_x[t * DM + d] + g_res[t * DM + d];
    }
    g_res[t * DM + d] = rv;

    float s = rv, s2 = rv * rv;
    #pragma unroll
    for (int o = 16; o; o >>= 1) {
        s  += __shfl_xor_sync(0xFFFFFFFFu, s,  o);
        s2 += __shfl_xor_sync(0xFFFFFFFFu, s2, o);
    }
    __shared__ float sh1[8], sh2[8];
    if ((d & 31) == 0) { sh1[d >> 5] = s; sh2[d >> 5] = s2; }
    __syncthreads();
    float ts = 0.f, ts2 = 0.f;
    #pragma unroll
    for (int i = 0; i < 8; i++) { ts += sh1[i]; ts2 += sh2[i]; }
    float mean = ts * (1.0f / DM);
    float var  = ts2 * (1.0f / DM) - mean * mean;
    float inv  = rsqrtf(var + EPSL);
    g_h[t * DM + d] = to_tf32((rv - mean) * inv * w[layer * DM + d] + b[layer * DM + d]);
}

// ---------------- causal depthwise conv (k=4) + silu (tf32-rounded out) ----------------
__global__ void k_conv(const float* __restrict__ cw, const float* __restrict__ cb, int layer) {
    int id = blockIdx.x * blockDim.x + threadIdx.x;
    if (id >= NT * DI) return;
    int d = id % DI, t = id / DI;
    int l = t % LEN, base = t - l;
    float4 wv = *(const float4*)(cw + (size_t)(layer * DI + d) * 4);
    float acc = cb[layer * DI + d];
    const float* src = g_xz + (size_t)base * (2 * DI) + d;
    if (l >= 3) {
        const float* p = src + (size_t)(l - 3) * (2 * DI);
        acc += p[0] * wv.x;
        acc += p[2 * DI] * wv.y;
        acc += p[4 * DI] * wv.z;
        acc += p[6 * DI] * wv.w;
    } else {
        const float w4[4] = {wv.x, wv.y, wv.z, wv.w};
        #pragma unroll
        for (int k = 0; k < 4; k++) {
            int ls = l - 3 + k;
            if (ls >= 0) acc += src[(size_t)ls * (2 * DI)] * w4[k];
        }
    }
    g_xc[id] = to_tf32(acc / (1.f + __expf(-acc)));
}

// ------- selective scan, fused dt_proj+softplus, software-pipelined -------
__global__ __launch_bounds__(128) void k_scan3(
        const float* __restrict__ A_log, const float* __restrict__ D_skip,
        const float* __restrict__ dtW_all, const float* __restrict__ dtb_all,
        int layer) {
    int id = blockIdx.x * blockDim.x + threadIdx.x;   // 2*BATCH*DI = 32768
    if (id >= 2 * BATCH * DI) return;
    const int half = id & 1;
    const int d = (id >> 1) % DI;
    const int b = id >> 10;
    const int s0 = half * 8;

    const float* wp = dtW_all + (size_t)(layer * DI + d) * DR;
    float4 w0 = *(const float4*)(wp);
    float4 w1 = *(const float4*)(wp + 4);
    float4 w2 = *(const float4*)(wp + 8);
    float4 w3 = *(const float4*)(wp + 12);
    const float dtb = dtb_all[layer * DI + d];

    float An[8];
    #pragma unroll
    for (int s = 0; s < 8; s++)
        An[s] = -__expf(A_log[(size_t)(layer * DI + d) * DS + s0 + s]);
    const float Dv = D_skip[layer * DI + d];

    float h[8];
    #pragma unroll
    for (int s = 0; s < 8; s++) h[s] = 0.f;

    int t = b * LEN;
    const float* dp = g_dbl + (size_t)t * 48;
    float  xv_n = g_xc[(size_t)t * DI + d];
    float  zv_n = g_xz[(size_t)t * (2 * DI) + DI + d];
    float4 r0n = *(const float4*)(dp);
    float4 r1n = *(const float4*)(dp + 4);
    float4 r2n = *(const float4*)(dp + 8);
    float4 r3n = *(const float4*)(dp + 12);
    float4 bBn0 = *(const float4*)(dp + 16 + s0);
    float4 bBn1 = *(const float4*)(dp + 20 + s0);
    float4 bCn0 = *(const float4*)(dp + 32 + s0);
    float4 bCn1 = *(const float4*)(dp + 36 + s0);

    for (int l = 0; l < LEN; l++, t++) {
        const float  xv = xv_n, zv = zv_n;
        const float4 r0 = r0n, r1 = r1n, r2 = r2n, r3 = r3n;
        const float4 bB0 = bBn0, bB1 = bBn1, bC0 = bCn0, bC1 = bCn1;

        if (l + 1 < LEN) {
            const float* dq = g_dbl + (size_t)(t + 1) * 48;
            xv_n = g_xc[(size_t)(t + 1) * DI + d];
            zv_n = g_xz[(size_t)(t + 1) * (2 * DI) + DI + d];
            r0n = *(const float4*)(dq);
            r1n = *(const float4*)(dq + 4);
            r2n = *(const float4*)(dq + 8);
            r3n = *(const float4*)(dq + 12);
            bBn0 = *(const float4*)(dq + 16 + s0);
            bBn1 = *(const float4*)(dq + 20 + s0);
            bCn0 = *(const float4*)(dq + 32 + s0);
            bCn1 = *(const float4*)(dq + 36 + s0);
        }

        float a = dtb;
        a += r0.x * w0.x + r0.y * w0.y + r0.z * w0.z + r0.w * w0.w;
        a += r1.x * w1.x + r1.y * w1.y + r1.z * w1.z + r1.w * w1.w;
        a += r2.x * w2.x + r2.y * w2.y + r2.z * w2.z + r2.w * w2.w;
        a += r3.x * w3.x + r3.y * w3.y + r3.z * w3.z + r3.w * w3.w;
        const float dtv = (a > 20.f) ? a : __logf(1.f + __expf(a));
        const float dx = dtv * xv;

        const float Bv[8] = {bB0.x, bB0.y, bB0.z, bB0.w, bB1.x, bB1.y, bB1.z, bB1.w};
        const float Cv[8] = {bC0.x, bC0.y, bC0.z, bC0.w, bC1.x, bC1.y, bC1.z, bC1.w};
        float y = 0.f;
        #pragma unroll
        for (int s = 0; s < 8; s++) {
            float da = __expf(dtv * An[s]);
            float hv = da * h[s] + dx * Bv[s];
            h[s] = hv;
            y += hv * Cv[s];
        }
        y += __shfl_xor_sync(0xFFFFFFFFu, y, 1);
        if (half == 0) {
            float sz = zv / (1.f + __expf(-zv));
            g_y[(size_t)t * DI + d] = to_tf32((y + xv * Dv) * sz);
        }
    }
}

// ---------------- final: residual add + RMSNorm (tf32-rounded out) ----------------
__global__ void k_final(const float* __restrict__ nw, const float* __restrict__ nb) {
    int t = blockIdx.x;
    int d = threadIdx.x;
    float rv = g_x[t * DM + d] + g_res[t * DM + d];
    float s2 = rv * rv;
    #pragma unroll
    for (int o = 16; o; o >>= 1) s2 += __shfl_xor_sync(0xFFFFFFFFu, s2, o);
    __shared__ float sh[8];
    if ((d & 31) == 0) sh[d >> 5] = s2;
    __syncthreads();
    float ts = 0.f;
    #pragma unroll
    for (int i = 0; i < 8; i++) ts += sh[i];
    float inv = rsqrtf(ts * (1.0f / DM) + EPSL);
    g_o[t * DM + d] = to_tf32(rv * inv * nw[d] + nb[d]);
}

// ---------------- host launcher ----------------
extern "C" void kernel_launch(void* const* d_in, const int* in_sizes, int n_in,
                              void* d_out, int out_size) {
    const float* coords   = (const float*)d_in[0];
    const float* emb_W    = (const float*)d_in[1];
    const float* emb_b    = (const float*)d_in[2];
    const float* ln_w     = (const float*)d_in[3];
    const float* ln_b     = (const float*)d_in[4];
    const float* in_W     = (const float*)d_in[5];
    const float* conv_W   = (const float*)d_in[6];
    const float* conv_b   = (const float*)d_in[7];
    const float* xproj_W  = (const float*)d_in[8];
    const float* dtproj_W = (const float*)d_in[9];
    const float* dtproj_b = (const float*)d_in[10];
    const float* A_log    = (const float*)d_in[11];
    const float* D_skip   = (const float*)d_in[12];
    const float* out_W    = (const float*)d_in[13];
    const float* normf_w  = (const float*)d_in[14];
    const float* normf_b  = (const float*)d_in[15];
    const float* head_W   = (const float*)d_in[16];
    float* logits = (float*)d_out;

    float *ph, *pxz, *pxc, *pdbl, *py, *px, *po;
    float *pwin, *pwxp, *pwout, *pwh;
    cudaGetSymbolAddress((void**)&ph,    g_h);
    cudaGetSymbolAddress((void**)&pxz,   g_xz);
    cudaGetSymbolAddress((void**)&pxc,   g_xc);
    cudaGetSymbolAddress((void**)&pdbl,  g_dbl);
    cudaGetSymbolAddress((void**)&py,    g_y);
    cudaGetSymbolAddress((void**)&px,    g_x);
    cudaGetSymbolAddress((void**)&po,    g_o);
    cudaGetSymbolAddress((void**)&pwin,  g_winW);
    cudaGetSymbolAddress((void**)&pwxp,  g_wxpW);
    cudaGetSymbolAddress((void**)&pwout, g_woutW);
    cudaGetSymbolAddress((void**)&pwh,   g_whW);

    // pre-round weights to tf32 (once per launch)
    k_round<<<(NL*2*DI*DM + 255)/256, 256>>>(in_W,    pwin,  NL*2*DI*DM);
    k_round<<<(NL*48*DI   + 255)/256, 256>>>(xproj_W, pwxp,  NL*48*DI);
    k_round<<<(NL*DM*DI   + 255)/256, 256>>>(out_W,   pwout, NL*DM*DI);
    k_round<<<(300*DM     + 255)/256, 256>>>(head_W,  pwh,   300*DM);

    for (int layer = 0; layer < NL; layer++) {
        // residual add + layernorm (layer 0 computes the embedding inline)
        k_ln<<<NT, DM>>>(ln_w, ln_b, coords, emb_W, emb_b, layer);
        // in_proj: (9600,256)x(1024,256)^T
        mmagemm<<<dim3(1024 / 128, NT / 128), 256>>>(
            ph, DM, pwin + (size_t)layer * 2 * DI * DM, pxz, 2 * DI, DM, 2 * DI);
        k_conv<<<(NT * DI + 255) / 256, 256>>>(conv_W, conv_b, layer);
        // x_proj: (9600,512)x(48,512)^T — BM=64 kernel
        mmagemm64<<<dim3(1, NT / 64), 256>>>(
            pxc, DI, pwxp + (size_t)layer * 48 * DI, pdbl, 48, DI, 48);
        // fused dt_proj + softplus + scan + D-skip + silu gate
        k_scan3<<<2 * BATCH * DI / 128, 128>>>(A_log, D_skip, dtproj_W, dtproj_b, layer);
        // out_proj: (9600,512)x(256,512)^T
        mmagemm<<<dim3(DM / 128, NT / 128), 256>>>(
            py, DI, pwout + (size_t)layer * DM * DI, px, DM, DI, DM);
    }

    k_final<<<NT, DM>>>(normf_w, normf_b);
    // head: (9600,256)x(300,256)^T
    mmagemm<<<dim3(3, NT / 128), 256>>>(
        po, DM, pwh, logits, 300, DM, 300);
}

// round 16
// speedup vs baseline: 1.1280x; 1.0129x over previous
#include <cuda_runtime.h>
#include <math.h>
#include <stdint.h>

#define BATCH 32
#define LEN   300
#define DM    256
#define DI    512
#define DS    16
#define DR    16
#define NL    4
#define NT    (BATCH * LEN)   // 9600
#define EPSL  1e-5f

// ---------------- scratch ----------------
__device__ float g_x  [NT * DM];
__device__ float g_res[NT * DM];
__device__ float g_h  [NT * DM];
__device__ float g_xz [NT * 2 * DI];
__device__ float g_xc [NT * DI];
__device__ float g_dbl[NT * 48];
__device__ float g_y  [NT * DI];
__device__ float g_o  [NT * DM];
// pre-rounded (tf32) weights
__device__ float g_winW [NL * 2 * DI * DM];
__device__ float g_wxpW [NL * 48 * DI];
__device__ float g_woutW[NL * DM * DI];
__device__ float g_whW  [300 * DM];

#define N_IN  (NL * 2 * DI * DM)
#define N_XP  (NL * 48 * DI)
#define N_OUT (NL * DM * DI)
#define N_HD  (300 * DM)

// ---------------- helpers ----------------
__device__ __forceinline__ float to_tf32(float x) {
    float r;
    asm("cvt.rna.tf32.f32 %0, %1;" : "=f"(r) : "f"(x));
    return r;
}
__device__ __forceinline__ uint32_t s2u(const void* p) {
    uint32_t a;
    asm("{ .reg .u64 t; cvta.to.shared.u64 t, %1; cvt.u32.u64 %0, t; }" : "=r"(a) : "l"(p));
    return a;
}
__device__ __forceinline__ void cp16(uint32_t dst, const void* src, int srcsz) {
    asm volatile("cp.async.cg.shared.global [%0], [%1], 16, %2;"
                 :: "r"(dst), "l"(src), "r"(srcsz) : "memory");
}
#define CP_COMMIT() asm volatile("cp.async.commit_group;" ::: "memory")
#define CP_WAIT0()  asm volatile("cp.async.wait_group 0;" ::: "memory")

__device__ __forceinline__ void mma_tf32_16x8x8(
        float& d0, float& d1, float& d2, float& d3,
        uint32_t a0, uint32_t a1, uint32_t a2, uint32_t a3,
        uint32_t b0, uint32_t b1) {
    asm volatile(
        "mma.sync.aligned.m16n8k8.row.col.f32.tf32.tf32.f32 "
        "{%0,%1,%2,%3}, {%4,%5,%6,%7}, {%8,%9}, {%0,%1,%2,%3};"
        : "+f"(d0), "+f"(d1), "+f"(d2), "+f"(d3)
        : "r"(a0), "r"(a1), "r"(a2), "r"(a3), "r"(b0), "r"(b1));
}

// ---------------- merged weight pre-round (one launch) ----------------
__global__ void k_round_all(const float* __restrict__ w_in, const float* __restrict__ w_xp,
                            const float* __restrict__ w_out, const float* __restrict__ w_hd) {
    int i = blockIdx.x * blockDim.x + threadIdx.x;
    if (i < N_IN) { g_winW[i] = to_tf32(w_in[i]); return; }
    i -= N_IN;
    if (i < N_XP) { g_wxpW[i] = to_tf32(w_xp[i]); return; }
    i -= N_XP;
    if (i < N_OUT) { g_woutW[i] = to_tf32(w_out[i]); return; }
    i -= N_OUT;
    if (i < N_HD) { g_whW[i] = to_tf32(w_hd[i]); }
}

// ================ TF32 MMA GEMM, BM=128, cp.async double-buffered ================
#define SA 20
__global__ __launch_bounds__(256, 2) void mmagemm(
        const float* __restrict__ A, int lda,
        const float* __restrict__ Bw,
        float* __restrict__ C, int N, int K, int ldc) {
    __shared__ float As[2][128 * SA];
    __shared__ float Bs[2][128 * SA];

    const int tid  = threadIdx.x;
    const int lane = tid & 31;
    const int wid  = tid >> 5;
    const int wm   = wid >> 1;
    const int wn   = wid & 1;
    const int bm   = blockIdx.y * 128;
    const int bn   = blockIdx.x * 128;

    const int trow = tid >> 1, tcol = (tid & 1) * 8;
    const int bsz  = ((bn + trow) < N) ? 16 : 0;

    const float* Ag = A + (size_t)(bm + trow) * lda + tcol;
    const float* Bg = Bw + (size_t)(bn + trow) * K + tcol;
    const uint32_t sAoff = (uint32_t)(trow * SA + tcol) * 4u;

    float acc[2][8][4];
    #pragma unroll
    for (int mt = 0; mt < 2; mt++)
        #pragma unroll
        for (int nt = 0; nt < 8; nt++)
            #pragma unroll
            for (int e = 0; e < 4; e++) acc[mt][nt][e] = 0.f;

    {
        uint32_t da = s2u(As[0]) + sAoff;
        uint32_t db = s2u(Bs[0]) + sAoff;
        cp16(da, Ag, 16); cp16(da + 16, Ag + 4, 16);
        cp16(db, Bg, bsz); cp16(db + 16, Bg + 4, bsz);
        CP_COMMIT();
    }
    CP_WAIT0();
    __syncthreads();

    const int qr = lane >> 2, qc = lane & 3;
    const int KT = K >> 4;
    for (int kt = 0; kt < KT; kt++) {
        const int cur = kt & 1;
        if (kt + 1 < KT) {
            const int off = (kt + 1) * 16;
            uint32_t da = s2u(As[cur ^ 1]) + sAoff;
            uint32_t db = s2u(Bs[cur ^ 1]) + sAoff;
            cp16(da, Ag + off, 16); cp16(da + 16, Ag + off + 4, 16);
            cp16(db, Bg + off, bsz); cp16(db + 16, Bg + off + 4, bsz);
            CP_COMMIT();
        }
        #pragma unroll
        for (int ks = 0; ks < 2; ks++) {
            const int k0 = ks * 8;
            uint32_t af[2][4];
            #pragma unroll
            for (int mt = 0; mt < 2; mt++) {
                const int r = wm * 32 + mt * 16 + qr;
                af[mt][0] = __float_as_uint(As[cur][(r    ) * SA + k0 + qc    ]);
                af[mt][1] = __float_as_uint(As[cur][(r + 8) * SA + k0 + qc    ]);
                af[mt][2] = __float_as_uint(As[cur][(r    ) * SA + k0 + qc + 4]);
                af[mt][3] = __float_as_uint(As[cur][(r + 8) * SA + k0 + qc + 4]);
            }
            #pragma unroll
            for (int nt = 0; nt < 8; nt++) {
                const int c = wn * 64 + nt * 8 + qr;
                uint32_t b0 = __float_as_uint(Bs[cur][c * SA + k0 + qc    ]);
                uint32_t b1 = __float_as_uint(Bs[cur][c * SA + k0 + qc + 4]);
                mma_tf32_16x8x8(acc[0][nt][0], acc[0][nt][1], acc[0][nt][2], acc[0][nt][3],
                                af[0][0], af[0][1], af[0][2], af[0][3], b0, b1);
                mma_tf32_16x8x8(acc[1][nt][0], acc[1][nt][1], acc[1][nt][2], acc[1][nt][3],
                                af[1][0], af[1][1], af[1][2], af[1][3], b0, b1);
            }
        }
        if (kt + 1 < KT) {
            CP_WAIT0();
            __syncthreads();
        }
    }

    #pragma unroll
    for (int mt = 0; mt < 2; mt++) {
        const int r0 = bm + wm * 32 + mt * 16 + qr;
        #pragma unroll
        for (int nt = 0; nt < 8; nt++) {
            const int c0 = bn + wn * 64 + nt * 8 + qc * 2;
            if (c0 + 1 < N) {
                *(float2*)(C + (size_t)r0 * ldc + c0) =
                    make_float2(acc[mt][nt][0], acc[mt][nt][1]);
                *(float2*)(C + (size_t)(r0 + 8) * ldc + c0) =
                    make_float2(acc[mt][nt][2], acc[mt][nt][3]);
            } else if (c0 < N) {
                C[(size_t)r0 * ldc + c0] = acc[mt][nt][0];
                C[(size_t)(r0 + 8) * ldc + c0] = acc[mt][nt][2];
            }
        }
    }
}

// ================ TF32 MMA GEMM, BM=64, cp.async (high occupancy) ================
__global__ __launch_bounds__(256, 3) void mmagemm64(
        const float* __restrict__ A, int lda,
        const float* __restrict__ Bw,
        float* __restrict__ C, int N, int K, int ldc) {
    __shared__ float As[2][64 * SA];
    __shared__ float Bs[2][128 * SA];

    const int tid  = threadIdx.x;
    const int lane = tid & 31;
    const int wid  = tid >> 5;
    const int wm   = wid >> 2;
    const int wn   = wid & 3;
    const int bm   = blockIdx.y * 64;
    const int bn   = blockIdx.x * 128;

    const int arow = tid >> 2, acol = (tid & 3) * 4;
    const int brow = tid >> 1, bcol = (tid & 1) * 8;
    const int bsz  = ((bn + brow) < N) ? 16 : 0;

    const float* Ag = A + (size_t)(bm + arow) * lda + acol;
    const float* Bg = Bw + (size_t)(bn + brow) * K + bcol;
    const uint32_t sAof = (uint32_t)(arow * SA + acol) * 4u;
    const uint32_t sBof = (uint32_t)(brow * SA + bcol) * 4u;

    float acc[2][4][4];
    #pragma unroll
    for (int mt = 0; mt < 2; mt++)
        #pragma unroll
        for (int nt = 0; nt < 4; nt++)
            #pragma unroll
            for (int e = 0; e < 4; e++) acc[mt][nt][e] = 0.f;

    {
        cp16(s2u(As[0]) + sAof, Ag, 16);
        uint32_t db = s2u(Bs[0]) + sBof;
        cp16(db, Bg, bsz); cp16(db + 16, Bg + 4, bsz);
        CP_COMMIT();
    }
    CP_WAIT0();
    __syncthreads();

    const int qr = lane >> 2, qc = lane & 3;
    const int KT = K >> 4;
    for (int kt = 0; kt < KT; kt++) {
        const int cur = kt & 1;
        if (kt + 1 < KT) {
            const int off = (kt + 1) * 16;
            cp16(s2u(As[cur ^ 1]) + sAof, Ag + off, 16);
            uint32_t db = s2u(Bs[cur ^ 1]) + sBof;
            cp16(db, Bg + off, bsz); cp16(db + 16, Bg + off + 4, bsz);
            CP_COMMIT();
        }
        #pragma unroll
        for (int ks = 0; ks < 2; ks++) {
            const int k0 = ks * 8;
            uint32_t af[2][4];
            #pragma unroll
            for (int mt = 0; mt < 2; mt++) {
                const int r = wm * 32 + mt * 16 + qr;
                af[mt][0] = __float_as_uint(As[cur][(r    ) * SA + k0 + qc    ]);
                af[mt][1] = __float_as_uint(As[cur][(r + 8) * SA + k0 + qc    ]);
                af[mt][2] = __float_as_uint(As[cur][(r    ) * SA + k0 + qc + 4]);
                af[mt][3] = __float_as_uint(As[cur][(r + 8) * SA + k0 + qc + 4]);
            }
            #pragma unroll
            for (int nt = 0; nt < 4; nt++) {
                const int c = wn * 32 + nt * 8 + qr;
                uint32_t b0 = __float_as_uint(Bs[cur][c * SA + k0 + qc    ]);
                uint32_t b1 = __float_as_uint(Bs[cur][c * SA + k0 + qc + 4]);
                mma_tf32_16x8x8(acc[0][nt][0], acc[0][nt][1], acc[0][nt][2], acc[0][nt][3],
                                af[0][0], af[0][1], af[0][2], af[0][3], b0, b1);
                mma_tf32_16x8x8(acc[1][nt][0], acc[1][nt][1], acc[1][nt][2], acc[1][nt][3],
                                af[1][0], af[1][1], af[1][2], af[1][3], b0, b1);
            }
        }
        if (kt + 1 < KT) {
            CP_WAIT0();
            __syncthreads();
        }
    }

    #pragma unroll
    for (int mt = 0; mt < 2; mt++) {
        const int r0 = bm + wm * 32 + mt * 16 + qr;
        #pragma unroll
        for (int nt = 0; nt < 4; nt++) {
            const int c0 = bn + wn * 32 + nt * 8 + qc * 2;
            if (c0 + 1 < N) {
                *(float2*)(C + (size_t)r0 * ldc + c0) =
                    make_float2(acc[mt][nt][0], acc[mt][nt][1]);
                *(float2*)(C + (size_t)(r0 + 8) * ldc + c0) =
                    make_float2(acc[mt][nt][2], acc[mt][nt][3]);
            } else if (c0 < N) {
                C[(size_t)r0 * ldc + c0] = acc[mt][nt][0];
                C[(size_t)(r0 + 8) * ldc + c0] = acc[mt][nt][2];
            }
        }
    }
}

// ---------------- residual add + layernorm (layer 0: embed inline) ----------------
__global__ void k_ln(const float* __restrict__ w, const float* __restrict__ b,
                     const float* __restrict__ coords,
                     const float* __restrict__ emb_W, const float* __restrict__ emb_b,
                     int layer) {
    int t = blockIdx.x;
    int d = threadIdx.x;
    float rv;
    if (layer == 0) {
        float c0 = coords[t * 2 + 0], c1 = coords[t * 2 + 1];
        rv = c0 * emb_W[d * 2 + 0] + c1 * emb_W[d * 2 + 1] + emb_b[d];
    } else {
        rv = g_x[t * DM + d] + g_res[t * DM + d];
    }
    g_res[t * DM + d] = rv;

    float s = rv, s2 = rv * rv;
    #pragma unroll
    for (int o = 16; o; o >>= 1) {
        s  += __shfl_xor_sync(0xFFFFFFFFu, s,  o);
        s2 += __shfl_xor_sync(0xFFFFFFFFu, s2, o);
    }
    __shared__ float sh1[8], sh2[8];
    if ((d & 31) == 0) { sh1[d >> 5] = s; sh2[d >> 5] = s2; }
    __syncthreads();
    float ts = 0.f, ts2 = 0.f;
    #pragma unroll
    for (int i = 0; i < 8; i++) { ts += sh1[i]; ts2 += sh2[i]; }
    float mean = ts * (1.0f / DM);
    float var  = ts2 * (1.0f / DM) - mean * mean;
    float inv  = rsqrtf(var + EPSL);
    g_h[t * DM + d] = to_tf32((rv - mean) * inv * w[layer * DM + d] + b[layer * DM + d]);
}

// ---------------- causal depthwise conv (k=4) + silu (tf32-rounded out) ----------------
__global__ void k_conv(const float* __restrict__ cw, const float* __restrict__ cb, int layer) {
    int id = blockIdx.x * blockDim.x + threadIdx.x;
    if (id >= NT * DI) return;
    int d = id % DI, t = id / DI;
    int l = t % LEN, base = t - l;
    float4 wv = *(const float4*)(cw + (size_t)(layer * DI + d) * 4);
    float acc = cb[layer * DI + d];
    const float* src = g_xz + (size_t)base * (2 * DI) + d;
    if (l >= 3) {
        const float* p = src + (size_t)(l - 3) * (2 * DI);
        acc += p[0] * wv.x;
        acc += p[2 * DI] * wv.y;
        acc += p[4 * DI] * wv.z;
        acc += p[6 * DI] * wv.w;
    } else {
        const float w4[4] = {wv.x, wv.y, wv.z, wv.w};
        #pragma unroll
        for (int k = 0; k < 4; k++) {
            int ls = l - 3 + k;
            if (ls >= 0) acc += src[(size_t)ls * (2 * DI)] * w4[k];
        }
    }
    g_xc[id] = to_tf32(acc / (1.f + __expf(-acc)));
}

// ------- selective scan, fused dt_proj+softplus, software-pipelined -------
__global__ __launch_bounds__(128) void k_scan3(
        const float* __restrict__ A_log, const float* __restrict__ D_skip,
        const float* __restrict__ dtW_all, const float* __restrict__ dtb_all,
        int layer) {
    int id = blockIdx.x * blockDim.x + threadIdx.x;   // 2*BATCH*DI = 32768
    if (id >= 2 * BATCH * DI) return;
    const int half = id & 1;
    const int d = (id >> 1) % DI;
    const int b = id >> 10;
    const int s0 = half * 8;

    const float* wp = dtW_all + (size_t)(layer * DI + d) * DR;
    float4 w0 = *(const float4*)(wp);
    float4 w1 = *(const float4*)(wp + 4);
    float4 w2 = *(const float4*)(wp + 8);
    float4 w3 = *(const float4*)(wp + 12);
    const float dtb = dtb_all[layer * DI + d];

    float An[8];
    #pragma unroll
    for (int s = 0; s < 8; s++)
        An[s] = -__expf(A_log[(size_t)(layer * DI + d) * DS + s0 + s]);
    const float Dv = D_skip[layer * DI + d];

    float h[8];
    #pragma unroll
    for (int s = 0; s < 8; s++) h[s] = 0.f;

    int t = b * LEN;
    const float* dp = g_dbl + (size_t)t * 48;
    float  xv_n = g_xc[(size_t)t * DI + d];
    float  zv_n = g_xz[(size_t)t * (2 * DI) + DI + d];
    float4 r0n = *(const float4*)(dp);
    float4 r1n = *(const float4*)(dp + 4);
    float4 r2n = *(const float4*)(dp + 8);
    float4 r3n = *(const float4*)(dp + 12);
    float4 bBn0 = *(const float4*)(dp + 16 + s0);
    float4 bBn1 = *(const float4*)(dp + 20 + s0);
    float4 bCn0 = *(const float4*)(dp + 32 + s0);
    float4 bCn1 = *(const float4*)(dp + 36 + s0);

    for (int l = 0; l < LEN; l++, t++) {
        const float  xv = xv_n, zv = zv_n;
        const float4 r0 = r0n, r1 = r1n, r2 = r2n, r3 = r3n;
        const float4 bB0 = bBn0, bB1 = bBn1, bC0 = bCn0, bC1 = bCn1;

        if (l + 1 < LEN) {
            const float* dq = g_dbl + (size_t)(t + 1) * 48;
            xv_n = g_xc[(size_t)(t + 1) * DI + d];
            zv_n = g_xz[(size_t)(t + 1) * (2 * DI) + DI + d];
            r0n = *(const float4*)(dq);
            r1n = *(const float4*)(dq + 4);
            r2n = *(const float4*)(dq + 8);
            r3n = *(const float4*)(dq + 12);
            bBn0 = *(const float4*)(dq + 16 + s0);
            bBn1 = *(const float4*)(dq + 20 + s0);
            bCn0 = *(const float4*)(dq + 32 + s0);
            bCn1 = *(const float4*)(dq + 36 + s0);
        }

        float a = dtb;
        a += r0.x * w0.x + r0.y * w0.y + r0.z * w0.z + r0.w * w0.w;
        a += r1.x * w1.x + r1.y * w1.y + r1.z * w1.z + r1.w * w1.w;
        a += r2.x * w2.x + r2.y * w2.y + r2.z * w2.z + r2.w * w2.w;
        a += r3.x * w3.x + r3.y * w3.y + r3.z * w3.z + r3.w * w3.w;
        const float dtv = (a > 20.f) ? a : __logf(1.f + __expf(a));
        const float dx = dtv * xv;

        const float Bv[8] = {bB0.x, bB0.y, bB0.z, bB0.w, bB1.x, bB1.y, bB1.z, bB1.w};
        const float Cv[8] = {bC0.x, bC0.y, bC0.z, bC0.w, bC1.x, bC1.y, bC1.z, bC1.w};
        float y = 0.f;
        #pragma unroll
        for (int s = 0; s < 8; s++) {
            float da = __expf(dtv * An[s]);
            float hv = da * h[s] + dx * Bv[s];
            h[s] = hv;
            y += hv * Cv[s];
        }
        y += __shfl_xor_sync(0xFFFFFFFFu, y, 1);
        if (half == 0) {
            float sz = zv / (1.f + __expf(-zv));
            g_y[(size_t)t * DI + d] = to_tf32((y + xv * Dv) * sz);
        }
    }
}

// ---------------- final: residual add + RMSNorm (tf32-rounded out) ----------------
__global__ void k_final(const float* __restrict__ nw, const float* __restrict__ nb) {
    int t = blockIdx.x;
    int d = threadIdx.x;
    float rv = g_x[t * DM + d] + g_res[t * DM + d];
    float s2 = rv * rv;
    #pragma unroll
    for (int o = 16; o; o >>= 1) s2 += __shfl_xor_sync(0xFFFFFFFFu, s2, o);
    __shared__ float sh[8];
    if ((d & 31) == 0) sh[d >> 5] = s2;
    __syncthreads();
    float ts = 0.f;
    #pragma unroll
    for (int i = 0; i < 8; i++) ts += sh[i];
    float inv = rsqrtf(ts * (1.0f / DM) + EPSL);
    g_o[t * DM + d] = to_tf32(rv * inv * nw[d] + nb[d]);
}

// ---------------- host launcher ----------------
extern "C" void kernel_launch(void* const* d_in, const int* in_sizes, int n_in,
                              void* d_out, int out_size) {
    const float* coords   = (const float*)d_in[0];
    const float* emb_W    = (const float*)d_in[1];
    const float* emb_b    = (const float*)d_in[2];
    const float* ln_w     = (const float*)d_in[3];
    const float* ln_b     = (const float*)d_in[4];
    const float* in_W     = (const float*)d_in[5];
    const float* conv_W   = (const float*)d_in[6];
    const float* conv_b   = (const float*)d_in[7];
    const float* xproj_W  = (const float*)d_in[8];
    const float* dtproj_W = (const float*)d_in[9];
    const float* dtproj_b = (const float*)d_in[10];
    const float* A_log    = (const float*)d_in[11];
    const float* D_skip   = (const float*)d_in[12];
    const float* out_W    = (const float*)d_in[13];
    const float* normf_w  = (const float*)d_in[14];
    const float* normf_b  = (const float*)d_in[15];
    const float* head_W   = (const float*)d_in[16];
    float* logits = (float*)d_out;

    float *ph, *pxz, *pxc, *pdbl, *py, *px, *po;
    float *pwin, *pwxp, *pwout, *pwh;
    cudaGetSymbolAddress((void**)&ph,    g_h);
    cudaGetSymbolAddress((void**)&pxz,   g_xz);
    cudaGetSymbolAddress((void**)&pxc,   g_xc);
    cudaGetSymbolAddress((void**)&pdbl,  g_dbl);
    cudaGetSymbolAddress((void**)&py,    g_y);
    cudaGetSymbolAddress((void**)&px,    g_x);
    cudaGetSymbolAddress((void**)&po,    g_o);
    cudaGetSymbolAddress((void**)&pwin,  g_winW);
    cudaGetSymbolAddress((void**)&pwxp,  g_wxpW);
    cudaGetSymbolAddress((void**)&pwout, g_woutW);
    cudaGetSymbolAddress((void**)&pwh,   g_whW);

    // lazily-created side stream + events (identical work every call)
    static cudaStream_t s_side = nullptr;
    static cudaEvent_t  ev_fork = nullptr, ev_join = nullptr;
    if (s_side == nullptr) {
        cudaStreamCreateWithFlags(&s_side, cudaStreamNonBlocking);
        cudaEventCreateWithFlags(&ev_fork, cudaEventDisableTiming);
        cudaEventCreateWithFlags(&ev_join, cudaEventDisableTiming);
    }

    // fork: weight rounding on side stream, layer-0 LN on main stream
    cudaEventRecord(ev_fork, 0);
    cudaStreamWaitEvent(s_side, ev_fork, 0);
    k_round_all<<<(N_IN + N_XP + N_OUT + N_HD + 255) / 256, 256, 0, s_side>>>(
        in_W, xproj_W, out_W, head_W);
    cudaEventRecord(ev_join, s_side);

    for (int layer = 0; layer < NL; layer++) {
        // residual add + layernorm (layer 0 computes the embedding inline)
        k_ln<<<NT, DM>>>(ln_w, ln_b, coords, emb_W, emb_b, layer);

        if (layer == 0) cudaStreamWaitEvent(0, ev_join, 0);   // weights ready

        // fork after LN: z-half GEMM on side stream, xi-half chain on main
        cudaEventRecord(ev_fork, 0);
        cudaStreamWaitEvent(s_side, ev_fork, 0);
        // in_proj z-half: columns 512..1023  (not needed until the scan's gate)
        mmagemm<<<dim3(DI / 128, NT / 128), 256, 0, s_side>>>(
            ph, DM, pwin + (size_t)layer * 2 * DI * DM + (size_t)DI * DM,
            pxz + DI, DI, DM, 2 * DI);
        cudaEventRecord(ev_join, s_side);

        // in_proj xi-half: columns 0..511
        mmagemm<<<dim3(DI / 128, NT / 128), 256>>>(
            ph, DM, pwin + (size_t)layer * 2 * DI * DM, pxz, DI, DM, 2 * DI);
        k_conv<<<(NT * DI + 255) / 256, 256>>>(conv_W, conv_b, layer);
        // x_proj: (9600,512)x(48,512)^T — BM=64 kernel
        mmagemm64<<<dim3(1, NT / 64), 256>>>(
            pxc, DI, pwxp + (size_t)layer * 48 * DI, pdbl, 48, DI, 48);

        // join: scan needs the z-half
        cudaStreamWaitEvent(0, ev_join, 0);
        // fused dt_proj + softplus + scan + D-skip + silu gate
        k_scan3<<<2 * BATCH * DI / 128, 128>>>(A_log, D_skip, dtproj_W, dtproj_b, layer);
        // out_proj: (9600,512)x(256,512)^T
        mmagemm<<<dim3(DM / 128, NT / 128), 256>>>(
            py, DI, pwout + (size_t)layer * DM * DI, px, DM, DI, DM);
    }

    k_final<<<NT, DM>>>(normf_w, normf_b);
    // head: (9600,256)x(300,256)^T
    mmagemm<<<dim3(3, NT / 128), 256>>>(
        po, DM, pwh, logits, 300, DM, 300);
}